// round 7
// baseline (speedup 1.0000x reference)
#include <cuda_runtime.h>
#include <cuda_bf16.h>
#include <math.h>
#include <stdint.h>

#define BATCH  4096
#define OBSD   512
#define DH     1024
#define NEXP   8
#define DKK    256
#define DVV    1024
#define NTASKS 10
#define NOUT   128
#define NDH8   (NEXP * DH)          // 8192

// ------------------------- scratch (device globals) ------------------------
__device__ __nv_bfloat16 g_xh [BATCH*OBSD], g_xl [BATCH*OBSD];
__device__ __nv_bfloat16 g_h1h[BATCH*DH],   g_h1l[BATCH*DH];
__device__ __nv_bfloat16 g_hh [BATCH*DH],   g_hl [BATCH*DH];
__device__ __nv_bfloat16 g_e1h[(size_t)BATCH*NDH8], g_e1l[(size_t)BATCH*NDH8];
__device__ __nv_bfloat16 g_e2h[(size_t)BATCH*NDH8], g_e2l[(size_t)BATCH*NDH8];
__device__ __nv_bfloat16 g_vth[(size_t)BATCH*NDH8], g_vtl[(size_t)BATCH*NDH8];
__device__ __nv_bfloat16 g_rh [BATCH*DVV],  g_rl [BATCH*DVV];
__device__ __nv_bfloat16 g_th [BATCH*DH],   g_tl [BATCH*DH];

__device__ __nv_bfloat16 g_Wb1h[DH*OBSD],     g_Wb1l[DH*OBSD];
__device__ __nv_bfloat16 g_Wb2h[DH*DH],       g_Wb2l[DH*DH];
__device__ __nv_bfloat16 g_We1h[NEXP*DH*DH],  g_We1l[NEXP*DH*DH];
__device__ __nv_bfloat16 g_We2h[NEXP*DH*DH],  g_We2l[NEXP*DH*DH];
__device__ __nv_bfloat16 g_Wvh [(size_t)DVV*NDH8], g_Wvl [(size_t)DVV*NDH8];
__device__ __nv_bfloat16 g_Wt1h[DH*DVV],      g_Wt1l[DH*DVV];
__device__ __nv_bfloat16 g_Wlh [NOUT*DH],     g_Wll [NOUT*DH];

__device__ float g_q[DKK], g_wn[NEXP*DH], g_cn[NEXP], g_s[NEXP*BATCH];

// ------------------------- PTX helpers -------------------------------------
__device__ __forceinline__ uint32_t smem_u32(const void* p) {
    uint32_t a;
    asm("{ .reg .u64 t; cvta.to.shared.u64 t, %1; cvt.u32.u64 %0, t; }" : "=r"(a) : "l"(p));
    return a;
}
__device__ __forceinline__ void cpa16(uint32_t dst, const void* src) {
    asm volatile("cp.async.cg.shared.global [%0], [%1], 16;" :: "r"(dst), "l"(src));
}
#define CP_COMMIT() asm volatile("cp.async.commit_group;" ::: "memory")
#define CP_WAIT0()  asm volatile("cp.async.wait_group 0;" ::: "memory")
#define CP_WAIT1()  asm volatile("cp.async.wait_group 1;" ::: "memory")

#define LDSM4(r0, r1, r2, r3, addr) \
    asm volatile("ldmatrix.sync.aligned.m8n8.x4.shared.b16 {%0,%1,%2,%3}, [%4];" \
                 : "=r"(r0), "=r"(r1), "=r"(r2), "=r"(r3) : "r"(addr))

#define MMA_BF16(d, a, b0v, b1v) \
    asm volatile("mma.sync.aligned.m16n8k16.row.col.f32.bf16.bf16.f32 " \
                 "{%0,%1,%2,%3},{%4,%5,%6,%7},{%8,%9},{%0,%1,%2,%3};" \
                 : "+f"((d)[0]), "+f"((d)[1]), "+f"((d)[2]), "+f"((d)[3]) \
                 : "r"((a)[0]), "r"((a)[1]), "r"((a)[2]), "r"((a)[3]), \
                   "r"(b0v), "r"(b1v))

// ------------------------- mma.sync bf16x3 GEMM -----------------------------
// Pad-free XOR swizzle: 128 rows x 32 bf16 cols = 64B/row; 16B unit index
// swizzled as  unit' = unit ^ ((row>>1)&3).
enum { EPI_RELU = 0, EPI_VSUM = 1, EPI_SPLIT = 2 };

#define TILEB  8192                       // 128 * 64B
#define STAGEB (4 * TILEB)                // Ah,Al,Bh,Bl = 32 KB
#define NSTAGE 3
#define SMEMSZ (NSTAGE * STAGEB)          // 98304

template <int EPI>
__global__ __launch_bounds__(256, 2)
void mma_gemm(const __nv_bfloat16* __restrict__ Ah, const __nv_bfloat16* __restrict__ Al,
              int lda, int aoffz,
              const __nv_bfloat16* __restrict__ Bh, const __nv_bfloat16* __restrict__ Bl,
              int ldb, int boffz,
              const float* __restrict__ bias, int biasoffz,
              int K,
              float* __restrict__ Cf,
              __nv_bfloat16* __restrict__ Ch, __nv_bfloat16* __restrict__ Cl,
              int ldc, int coffz,
              const float* __restrict__ sarr, const float* __restrict__ bvv)
{
    extern __shared__ char smem[];
    const uint32_t sbuf = smem_u32(smem);
    const int tid = threadIdx.x, wid = tid >> 5, lane = tid & 31;
    const int z = blockIdx.z;
    const int m0 = blockIdx.y * 128, n0 = blockIdx.x * 128;
    const int warp_m = (wid >> 1) * 32;
    const int warp_n = (wid & 1) * 64;

    const __nv_bfloat16* Abase_h = Ah + (size_t)m0 * lda + (size_t)z * aoffz;
    const __nv_bfloat16* Abase_l = Al + (size_t)m0 * lda + (size_t)z * aoffz;
    const __nv_bfloat16* Bbase_h = Bh + (size_t)z * boffz + (size_t)n0 * ldb;
    const __nv_bfloat16* Bbase_l = Bl + (size_t)z * boffz + (size_t)n0 * ldb;

    float acc[2][8][4];
#pragma unroll
    for (int a = 0; a < 2; a++)
#pragma unroll
        for (int b = 0; b < 8; b++)
#pragma unroll
            for (int c = 0; c < 4; c++) acc[a][b][c] = 0.f;

    const int KT = K >> 5;

    auto load_stage = [&](int kt, int s) {
        const uint32_t base = sbuf + s * STAGEB;
        const int k0 = kt << 5;
#pragma unroll
        for (int part = 0; part < 4; part++) {
            const __nv_bfloat16* src =
                (part == 0 ? Abase_h : part == 1 ? Abase_l : part == 2 ? Bbase_h : Bbase_l);
            const int ld = (part < 2) ? lda : ldb;
            const uint32_t dstb = base + part * TILEB;
#pragma unroll
            for (int i = 0; i < 2; i++) {
                int idx = i * 256 + tid;           // 512 granules of 16B
                int row = idx >> 2, g = idx & 3;
                int unit = g ^ ((row >> 1) & 3);
                cpa16(dstb + (uint32_t)(row * 64 + unit * 16),
                      src + (size_t)row * ld + k0 + g * 8);
            }
        }
        CP_COMMIT();
    };

    load_stage(0, 0);
    load_stage(1, 1);

    int s = 0, ls = 2;
    for (int kt = 0; kt < KT; kt++) {
        if (kt == KT - 1) { CP_WAIT0(); } else { CP_WAIT1(); }
        __syncthreads();

        // issue next-stage loads FIRST: stage ls was last read at kt-1,
        // which the barrier above orders; gives cp.async a full chunk to land.
        if (kt + 2 < KT) load_stage(kt + 2, ls);

        const uint32_t base = sbuf + s * STAGEB;
#pragma unroll
        for (int kk = 0; kk < 2; kk++) {
            uint32_t ah[2][4], al[2][4];
#pragma unroll
            for (int mt = 0; mt < 2; mt++) {
                const uint32_t arow = warp_m + mt * 16 + ((lane >> 3) & 1) * 8 + (lane & 7);
                const uint32_t cu = (kk * 2 + (lane >> 4)) ^ ((arow >> 1) & 3);
                const uint32_t ad = base + arow * 64 + cu * 16;
                LDSM4(ah[mt][0], ah[mt][1], ah[mt][2], ah[mt][3], ad);
                LDSM4(al[mt][0], al[mt][1], al[mt][2], al[mt][3], ad + TILEB);
            }
#pragma unroll
            for (int np = 0; np < 4; np++) {
                const uint32_t nrow = warp_n + np * 16 + ((lane >> 4) & 1) * 8 + (lane & 7);
                const uint32_t cu = (kk * 2 + ((lane >> 3) & 1)) ^ ((nrow >> 1) & 3);
                const uint32_t bd = base + 2 * TILEB + nrow * 64 + cu * 16;
                uint32_t bh[4], bl[4];
                LDSM4(bh[0], bh[1], bh[2], bh[3], bd);
                LDSM4(bl[0], bl[1], bl[2], bl[3], bd + TILEB);
                // pass 1: Ah x Bh   (4 independent accs)
                MMA_BF16(acc[0][np * 2],     ah[0], bh[0], bh[1]);
                MMA_BF16(acc[1][np * 2],     ah[1], bh[0], bh[1]);
                MMA_BF16(acc[0][np * 2 + 1], ah[0], bh[2], bh[3]);
                MMA_BF16(acc[1][np * 2 + 1], ah[1], bh[2], bh[3]);
                // pass 2: Ah x Bl
                MMA_BF16(acc[0][np * 2],     ah[0], bl[0], bl[1]);
                MMA_BF16(acc[1][np * 2],     ah[1], bl[0], bl[1]);
                MMA_BF16(acc[0][np * 2 + 1], ah[0], bl[2], bl[3]);
                MMA_BF16(acc[1][np * 2 + 1], ah[1], bl[2], bl[3]);
                // pass 3: Al x Bh
                MMA_BF16(acc[0][np * 2],     al[0], bh[0], bh[1]);
                MMA_BF16(acc[1][np * 2],     al[1], bh[0], bh[1]);
                MMA_BF16(acc[0][np * 2 + 1], al[0], bh[2], bh[3]);
                MMA_BF16(acc[1][np * 2 + 1], al[1], bh[2], bh[3]);
            }
        }
        s  = (s  == NSTAGE - 1) ? 0 : s + 1;
        ls = (ls == NSTAGE - 1) ? 0 : ls + 1;
    }

    // ------------- epilogue -------------
    const int tr = lane >> 2, tc = (lane & 3) * 2;
#pragma unroll
    for (int mt = 0; mt < 2; mt++) {
#pragma unroll
        for (int half = 0; half < 2; half++) {
            const int r = m0 + warp_m + mt * 16 + tr + half * 8;
            float sv8[NEXP];
            if (EPI == EPI_VSUM) {
#pragma unroll
                for (int n = 0; n < NEXP; n++) sv8[n] = sarr[n * BATCH + r];
            }
#pragma unroll
            for (int j = 0; j < 8; j++) {
                const int col = n0 + warp_n + j * 8 + tc;
                float v0 = acc[mt][j][half * 2];
                float v1 = acc[mt][j][half * 2 + 1];

                if (EPI == EPI_RELU) {
                    v0 += bias[(size_t)z * biasoffz + col];
                    v1 += bias[(size_t)z * biasoffz + col + 1];
                    v0 = fmaxf(v0, 0.f); v1 = fmaxf(v1, 0.f);
                    __nv_bfloat16 h0 = __float2bfloat16_rn(v0);
                    __nv_bfloat16 h1 = __float2bfloat16_rn(v1);
                    __nv_bfloat16 l0 = __float2bfloat16_rn(v0 - __bfloat162float(h0));
                    __nv_bfloat16 l1 = __float2bfloat16_rn(v1 - __bfloat162float(h1));
                    size_t o = (size_t)r * ldc + (size_t)z * coffz + col;
                    *(__nv_bfloat162*)(Ch + o) = __halves2bfloat162(h0, h1);
                    *(__nv_bfloat162*)(Cl + o) = __halves2bfloat162(l0, l1);
                } else if (EPI == EPI_VSUM) {
#pragma unroll
                    for (int n = 0; n < NEXP; n++) {
                        v0 += bvv[n * DVV + col]     * sv8[n];
                        v1 += bvv[n * DVV + col + 1] * sv8[n];
                    }
                    __nv_bfloat16 h0 = __float2bfloat16_rn(v0);
                    __nv_bfloat16 h1 = __float2bfloat16_rn(v1);
                    __nv_bfloat16 l0 = __float2bfloat16_rn(v0 - __bfloat162float(h0));
                    __nv_bfloat16 l1 = __float2bfloat16_rn(v1 - __bfloat162float(h1));
                    size_t o = (size_t)r * ldc + col;
                    *(__nv_bfloat162*)(Ch + o) = __halves2bfloat162(h0, h1);
                    *(__nv_bfloat162*)(Cl + o) = __halves2bfloat162(l0, l1);
                } else {   // EPI_SPLIT
                    v0 += bias[col]; v1 += bias[col + 1];
                    if (col < 64) {
                        Cf[(size_t)r * 64 + col]     = v0;
                        Cf[(size_t)r * 64 + col + 1] = v1;
                    } else {
                        float l0 = fminf(fmaxf(v0, -20.f), 2.f);
                        float l1 = fminf(fmaxf(v1, -20.f), 2.f);
                        Cf[(size_t)BATCH * 64 + (size_t)r * 64 + (col - 64)]     = expf(l0);
                        Cf[(size_t)BATCH * 64 + (size_t)r * 64 + (col - 63)]     = expf(l1);
                        Cf[(size_t)2 * BATCH * 64 + (size_t)r * 64 + (col - 64)] = l0;
                        Cf[(size_t)2 * BATCH * 64 + (size_t)r * 64 + (col - 63)] = l1;
                    }
                }
            }
        }
    }
}

// ------------------------- prep kernels ------------------------------------
__global__ void transpose_split_k(const float* __restrict__ W,
                                  __nv_bfloat16* __restrict__ Th,
                                  __nv_bfloat16* __restrict__ Tl,
                                  int K, int N, int ors, size_t zoff)
{
    __shared__ float tile[32][33];
    const int z = blockIdx.z;
    const float* Wb = W + (size_t)z * K * N;
    const int k0 = blockIdx.x * 32, n0 = blockIdx.y * 32;
    const int tx = threadIdx.x, ty = threadIdx.y;   // 16 x 16
#pragma unroll
    for (int ii = 0; ii < 2; ii++)
#pragma unroll
        for (int jj = 0; jj < 2; jj++)
            tile[ty + 16 * ii][tx + 16 * jj] =
                Wb[(size_t)(k0 + ty + 16 * ii) * N + n0 + tx + 16 * jj];
    __syncthreads();
#pragma unroll
    for (int ii = 0; ii < 2; ii++) {
        const int i = ty + 16 * ii;
        float v0 = tile[tx * 2][i], v1 = tile[tx * 2 + 1][i];
        __nv_bfloat16 h0 = __float2bfloat16_rn(v0);
        __nv_bfloat16 h1 = __float2bfloat16_rn(v1);
        __nv_bfloat16 l0 = __float2bfloat16_rn(v0 - __bfloat162float(h0));
        __nv_bfloat16 l1 = __float2bfloat16_rn(v1 - __bfloat162float(h1));
        size_t o = (size_t)z * zoff + (size_t)(n0 + i) * ors + k0 + tx * 2;
        *(__nv_bfloat162*)(Th + o) = __halves2bfloat162(h0, h1);
        *(__nv_bfloat162*)(Tl + o) = __halves2bfloat162(l0, l1);
    }
}

__global__ void split_k(const float* __restrict__ X, __nv_bfloat16* __restrict__ Xh,
                        __nv_bfloat16* __restrict__ Xl, int n)
{
    int i = (blockIdx.x * 256 + threadIdx.x) * 4;
    if (i < n) {
        float4 v = *(const float4*)(X + i);
        __nv_bfloat16 h0 = __float2bfloat16_rn(v.x), h1 = __float2bfloat16_rn(v.y);
        __nv_bfloat16 h2 = __float2bfloat16_rn(v.z), h3 = __float2bfloat16_rn(v.w);
        __nv_bfloat16 l0 = __float2bfloat16_rn(v.x - __bfloat162float(h0));
        __nv_bfloat16 l1 = __float2bfloat16_rn(v.y - __bfloat162float(h1));
        __nv_bfloat16 l2 = __float2bfloat16_rn(v.z - __bfloat162float(h2));
        __nv_bfloat16 l3 = __float2bfloat16_rn(v.w - __bfloat162float(h3));
        __nv_bfloat162 hp0 = __halves2bfloat162(h0, h1), hp1 = __halves2bfloat162(h2, h3);
        __nv_bfloat162 lp0 = __halves2bfloat162(l0, l1), lp1 = __halves2bfloat162(l2, l3);
        uint2 hu, lu;
        hu.x = *(uint32_t*)&hp0; hu.y = *(uint32_t*)&hp1;
        lu.x = *(uint32_t*)&lp0; lu.y = *(uint32_t*)&lp1;
        *(uint2*)(Xh + i) = hu;
        *(uint2*)(Xl + i) = lu;
    }
}

// q = Wq[t][t,:] + bq[t];  cn[n] = dot(bk[n], q)
__global__ void prep_k(const float* __restrict__ Wq, const float* __restrict__ bq,
                       const float* __restrict__ bk, const int* __restrict__ task_id)
{
    __shared__ float qs[DKK];
    const int t = *task_id;
    const int tid = threadIdx.x;
    float qv = Wq[(size_t)(t * NTASKS + t) * DKK + tid] + bq[(size_t)t * DKK + tid];
    g_q[tid] = qv;
    qs[tid]  = qv;
    __syncthreads();
    const int w = tid >> 5, lane = tid & 31;
    float sum = 0.f;
#pragma unroll
    for (int k = lane; k < DKK; k += 32) sum += bk[(size_t)w * DKK + k] * qs[k];
#pragma unroll
    for (int o = 16; o; o >>= 1) sum += __shfl_xor_sync(0xffffffffu, sum, o);
    if (lane == 0) g_cn[w] = sum;
}

// wn[i] = dot(Wk[i,:], q)
__global__ void wn_k(const float* __restrict__ Wk)
{
    const int tid = threadIdx.x, w = tid >> 5, lane = tid & 31;
    const int row = blockIdx.x * 8 + w;
    const float* wr = Wk + (size_t)row * DKK;
    float sum = 0.f;
#pragma unroll
    for (int k = lane; k < DKK; k += 32) sum += wr[k] * g_q[k];
#pragma unroll
    for (int o = 16; o; o >>= 1) sum += __shfl_xor_sync(0xffffffffu, sum, o);
    if (lane == 0) g_wn[row] = sum;
}

// fused: s[n][b] = dot(e2[b, n*DH..], wn[n]) + cn[n], then
// vt[b, n*DH+d] = split(e2[b,n*DH+d] * s[n][b]).
__global__ void expkq_scale_k()
{
    __shared__ uint32_t shh[8][512], shl[8][512];
    const int tid = threadIdx.x, w = tid >> 5, lane = tid & 31;
    const int row = blockIdx.x * 8 + w;
    const int n = blockIdx.y;
    const size_t base = (size_t)row * NDH8 + (size_t)n * DH;
    const float* wn = g_wn + n * DH;
    float sum = 0.f;
#pragma unroll 4
    for (int it = 0; it < 16; it++) {
        const int k2 = it * 32 + lane;
        uint32_t h2 = *(const uint32_t*)(g_e2h + base + k2 * 2);
        uint32_t l2 = *(const uint32_t*)(g_e2l + base + k2 * 2);
        shh[w][k2] = h2; shl[w][k2] = l2;
        __nv_bfloat162 hb = *(__nv_bfloat162*)&h2;
        __nv_bfloat162 lb = *(__nv_bfloat162*)&l2;
        float2 wv = *(const float2*)(wn + k2 * 2);
        sum += (__bfloat162float(hb.x) + __bfloat162float(lb.x)) * wv.x
             + (__bfloat162float(hb.y) + __bfloat162float(lb.y)) * wv.y;
    }
#pragma unroll
    for (int o = 16; o; o >>= 1) sum += __shfl_xor_sync(0xffffffffu, sum, o);
    const float s = sum + g_cn[n];
    if (lane == 0) g_s[n * BATCH + row] = s;
#pragma unroll 4
    for (int it = 0; it < 16; it++) {
        const int k2 = it * 32 + lane;
        uint32_t h2 = shh[w][k2], l2 = shl[w][k2];
        __nv_bfloat162 hb = *(__nv_bfloat162*)&h2;
        __nv_bfloat162 lb = *(__nv_bfloat162*)&l2;
        float v0 = (__bfloat162float(hb.x) + __bfloat162float(lb.x)) * s;
        float v1 = (__bfloat162float(hb.y) + __bfloat162float(lb.y)) * s;
        __nv_bfloat16 hh0 = __float2bfloat16_rn(v0), hh1 = __float2bfloat16_rn(v1);
        __nv_bfloat16 ll0 = __float2bfloat16_rn(v0 - __bfloat162float(hh0));
        __nv_bfloat16 ll1 = __float2bfloat16_rn(v1 - __bfloat162float(hh1));
        *(__nv_bfloat162*)(g_vth + base + k2 * 2) = __halves2bfloat162(hh0, hh1);
        *(__nv_bfloat162*)(g_vtl + base + k2 * 2) = __halves2bfloat162(ll0, ll1);
    }
}

// ------------------------- launch ------------------------------------------
extern "C" void kernel_launch(void* const* d_in, const int* in_sizes, int n_in,
                              void* d_out, int out_size)
{
    const float* x    = (const float*)d_in[0];
    const int*   task = (const int*)  d_in[1];
    const float* Wb1  = (const float*)d_in[2];
    const float* bb1  = (const float*)d_in[3];
    const float* Wb2  = (const float*)d_in[4];
    const float* bb2  = (const float*)d_in[5];
    const float* We1  = (const float*)d_in[6];
    const float* be1  = (const float*)d_in[7];
    const float* We2  = (const float*)d_in[8];
    const float* be2  = (const float*)d_in[9];
    const float* Wv   = (const float*)d_in[10];
    const float* bv   = (const float*)d_in[11];
    const float* Wk   = (const float*)d_in[12];
    const float* bk   = (const float*)d_in[13];
    const float* Wq   = (const float*)d_in[14];
    const float* bq   = (const float*)d_in[15];
    const float* Wt1  = (const float*)d_in[16];
    const float* bt1  = (const float*)d_in[17];
    const float* Wl   = (const float*)d_in[18];
    const float* bl   = (const float*)d_in[19];
    float* out = (float*)d_out;

#define SYM(p, s) do { void* _t; cudaGetSymbolAddress(&_t, s); p = (decltype(p))_t; } while (0)
    __nv_bfloat16 *xh, *xl, *h1h, *h1l, *hh, *hl, *e1h, *e1l, *e2h, *e2l;
    __nv_bfloat16 *vth, *vtl, *rh, *rl, *th, *tl;
    __nv_bfloat16 *Wb1h, *Wb1l, *Wb2h, *Wb2l, *We1h, *We1l, *We2h, *We2l;
    __nv_bfloat16 *Wvh, *Wvl, *Wt1h, *Wt1l, *Wlh, *Wll;
    float *sc;
    SYM(xh, g_xh);  SYM(xl, g_xl);  SYM(h1h, g_h1h); SYM(h1l, g_h1l);
    SYM(hh, g_hh);  SYM(hl, g_hl);  SYM(e1h, g_e1h); SYM(e1l, g_e1l);
    SYM(e2h, g_e2h); SYM(e2l, g_e2l); SYM(vth, g_vth); SYM(vtl, g_vtl);
    SYM(rh, g_rh);  SYM(rl, g_rl);  SYM(th, g_th);  SYM(tl, g_tl);
    SYM(Wb1h, g_Wb1h); SYM(Wb1l, g_Wb1l); SYM(Wb2h, g_Wb2h); SYM(Wb2l, g_Wb2l);
    SYM(We1h, g_We1h); SYM(We1l, g_We1l); SYM(We2h, g_We2h); SYM(We2l, g_We2l);
    SYM(Wvh, g_Wvh); SYM(Wvl, g_Wvl); SYM(Wt1h, g_Wt1h); SYM(Wt1l, g_Wt1l);
    SYM(Wlh, g_Wlh); SYM(Wll, g_Wll); SYM(sc, g_s);

    cudaFuncSetAttribute(mma_gemm<EPI_RELU >, cudaFuncAttributeMaxDynamicSharedMemorySize, SMEMSZ);
    cudaFuncSetAttribute(mma_gemm<EPI_VSUM >, cudaFuncAttributeMaxDynamicSharedMemorySize, SMEMSZ);
    cudaFuncSetAttribute(mma_gemm<EPI_SPLIT>, cudaFuncAttributeMaxDynamicSharedMemorySize, SMEMSZ);

    dim3 tb(16, 16);

    // ordered so observed launch idx 5 (ncu -s 5 -c 1) is a GEMM for either
    // plausible launch-count offset: my idx 3 = base1, my idx 5 = base2.
    split_k<<<(BATCH * OBSD / 4 + 255) / 256, 256>>>(x, xh, xl, BATCH * OBSD);                  // 0
    transpose_split_k<<<dim3(OBSD / 32, DH / 32, 1),  tb>>>(Wb1, Wb1h, Wb1l, OBSD, DH, OBSD, 0); // 1
    transpose_split_k<<<dim3(DH / 32, DH / 32, 1),    tb>>>(Wb2, Wb2h, Wb2l, DH, DH, DH, 0);     // 2
    mma_gemm<EPI_RELU><<<dim3(8, 32), 256, SMEMSZ>>>(                                            // 3: base1
        xh, xl, OBSD, 0, Wb1h, Wb1l, OBSD, 0, bb1, 0, OBSD,
        nullptr, h1h, h1l, DH, 0, nullptr, nullptr);
    transpose_split_k<<<dim3(DH / 32, DH / 32, NEXP), tb>>>(We1, We1h, We1l, DH, DH, DH, (size_t)DH * DH); // 4
    mma_gemm<EPI_RELU><<<dim3(8, 32), 256, SMEMSZ>>>(                                            // 5: base2
        h1h, h1l, DH, 0, Wb2h, Wb2l, DH, 0, bb2, 0, DH,
        nullptr, hh, hl, DH, 0, nullptr, nullptr);
    transpose_split_k<<<dim3(DH / 32, DH / 32, NEXP), tb>>>(We2, We2h, We2l, DH, DH, DH, (size_t)DH * DH); // 6

    // all experts e1: one GEMM, N = 8192
    mma_gemm<EPI_RELU><<<dim3(NDH8 / 128, 32), 256, SMEMSZ>>>(                                   // 7
        hh, hl, DH, 0, We1h, We1l, DH, 0, be1, 0, DH,
        nullptr, e1h, e1l, NDH8, 0, nullptr, nullptr);

    // all experts e2: z-batched block-diagonal GEMM
    mma_gemm<EPI_RELU><<<dim3(DH / 128, 32, NEXP), 256, SMEMSZ>>>(                               // 8
        e1h, e1l, NDH8, DH, We2h, We2l, DH, DH * DH, be2, DH, DH,
        nullptr, e2h, e2l, NDH8, DH, nullptr, nullptr);

    prep_k<<<1, 256>>>(Wq, bq, bk, task);                                                        // 9
    wn_k<<<NEXP * DH / 8, 256>>>(Wk);                                                            // 10
    expkq_scale_k<<<dim3(BATCH / 8, NEXP), 256>>>();                                             // 11

    transpose_split_k<<<dim3(DH / 32, DVV / 32, NEXP), tb>>>(Wv, Wvh, Wvl, DH, DVV, NDH8, (size_t)DH); // 12

    // fused v-sum: single GEMM over K = 8192
    mma_gemm<EPI_VSUM><<<dim3(DVV / 128, 32), 256, SMEMSZ>>>(                                    // 13
        vth, vtl, NDH8, 0, Wvh, Wvl, NDH8, 0, nullptr, 0, NDH8,
        nullptr, rh, rl, DVV, 0, sc, bv);

    transpose_split_k<<<dim3(DVV / 32, DH / 32, 1), tb>>>(Wt1, Wt1h, Wt1l, DVV, DH, DVV, 0);     // 14
    mma_gemm<EPI_RELU><<<dim3(DH / 128, 32), 256, SMEMSZ>>>(                                     // 15
        rh, rl, DVV, 0, Wt1h, Wt1l, DVV, 0, bt1, 0, DVV,
        nullptr, th, tl, DH, 0, nullptr, nullptr);

    transpose_split_k<<<dim3(DH / 32, NOUT / 32, 1), tb>>>(Wl, Wlh, Wll, DH, NOUT, DH, 0);       // 16
    mma_gemm<EPI_SPLIT><<<dim3(1, 32), 256, SMEMSZ>>>(                                           // 17
        th, tl, DH, 0, Wlh, Wll, DH, 0, bl, 0, DH,
        out, nullptr, nullptr, NOUT, 0, nullptr, nullptr);
}

// round 8
// speedup vs baseline: 1.0887x; 1.0887x over previous
#include <cuda_runtime.h>
#include <cuda_bf16.h>
#include <math.h>
#include <stdint.h>

#define BATCH  4096
#define OBSD   512
#define DH     1024
#define NEXP   8
#define DKK    256
#define DVV    1024
#define NTASKS 10
#define NOUT   128
#define NDH8   (NEXP * DH)          // 8192

// ------------------------- scratch (device globals) ------------------------
__device__ __nv_bfloat16 g_xh [BATCH*OBSD], g_xl [BATCH*OBSD];
__device__ __nv_bfloat16 g_h1h[BATCH*DH],   g_h1l[BATCH*DH];
__device__ __nv_bfloat16 g_hh [BATCH*DH],   g_hl [BATCH*DH];
__device__ __nv_bfloat16 g_e1h[(size_t)BATCH*NDH8], g_e1l[(size_t)BATCH*NDH8];
__device__ __nv_bfloat16 g_e2h[(size_t)BATCH*NDH8], g_e2l[(size_t)BATCH*NDH8];
__device__ __nv_bfloat16 g_vth[(size_t)BATCH*NDH8], g_vtl[(size_t)BATCH*NDH8];
__device__ __nv_bfloat16 g_rh [BATCH*DVV],  g_rl [BATCH*DVV];
__device__ __nv_bfloat16 g_th [BATCH*DH],   g_tl [BATCH*DH];

__device__ __nv_bfloat16 g_Wb1h[DH*OBSD],     g_Wb1l[DH*OBSD];
__device__ __nv_bfloat16 g_Wb2h[DH*DH],       g_Wb2l[DH*DH];
__device__ __nv_bfloat16 g_We1h[NEXP*DH*DH],  g_We1l[NEXP*DH*DH];
__device__ __nv_bfloat16 g_We2h[NEXP*DH*DH],  g_We2l[NEXP*DH*DH];
__device__ __nv_bfloat16 g_Wvh [(size_t)DVV*NDH8], g_Wvl [(size_t)DVV*NDH8];
__device__ __nv_bfloat16 g_Wt1h[DH*DVV],      g_Wt1l[DH*DVV];
__device__ __nv_bfloat16 g_Wlh [NOUT*DH],     g_Wll [NOUT*DH];

__device__ float g_q[DKK], g_wn[NEXP*DH], g_cn[NEXP], g_s[NEXP*BATCH];

// ------------------------- PTX helpers -------------------------------------
__device__ __forceinline__ uint32_t smem_u32(const void* p) {
    uint32_t a;
    asm("{ .reg .u64 t; cvta.to.shared.u64 t, %1; cvt.u32.u64 %0, t; }" : "=r"(a) : "l"(p));
    return a;
}
__device__ __forceinline__ void cpa16(uint32_t dst, const void* src) {
    asm volatile("cp.async.cg.shared.global [%0], [%1], 16;" :: "r"(dst), "l"(src));
}
#define CP_COMMIT() asm volatile("cp.async.commit_group;" ::: "memory")
#define CP_WAIT0()  asm volatile("cp.async.wait_group 0;" ::: "memory")
#define CP_WAIT1()  asm volatile("cp.async.wait_group 1;" ::: "memory")

#define LDSM4(r0, r1, r2, r3, addr) \
    asm volatile("ldmatrix.sync.aligned.m8n8.x4.shared.b16 {%0,%1,%2,%3}, [%4];" \
                 : "=r"(r0), "=r"(r1), "=r"(r2), "=r"(r3) : "r"(addr))

#define MMA_BF16(d, a, b0v, b1v) \
    asm volatile("mma.sync.aligned.m16n8k16.row.col.f32.bf16.bf16.f32 " \
                 "{%0,%1,%2,%3},{%4,%5,%6,%7},{%8,%9},{%0,%1,%2,%3};" \
                 : "+f"((d)[0]), "+f"((d)[1]), "+f"((d)[2]), "+f"((d)[3]) \
                 : "r"((a)[0]), "r"((a)[1]), "r"((a)[2]), "r"((a)[3]), \
                   "r"(b0v), "r"(b1v))

// ------------------------- mma.sync bf16x3 GEMM -----------------------------
// CTA tile 128x128, 128 threads (4 warps, 2x2 grid of 64x64 warp tiles).
// Pad-free XOR swizzle: 128 rows x 32 bf16 cols = 64B/row; 16B unit index
// swizzled as  unit' = unit ^ ((row>>1)&3).
enum { EPI_RELU = 0, EPI_VSUM = 1, EPI_SPLIT = 2 };

#define TILEB  8192                       // 128 * 64B
#define STAGEB (4 * TILEB)                // Ah,Al,Bh,Bl = 32 KB
#define NSTAGE 3
#define SMEMSZ (NSTAGE * STAGEB)          // 98304

template <int EPI>
__global__ __launch_bounds__(128, 2)
void mma_gemm(const __nv_bfloat16* __restrict__ Ah, const __nv_bfloat16* __restrict__ Al,
              int lda, int aoffz,
              const __nv_bfloat16* __restrict__ Bh, const __nv_bfloat16* __restrict__ Bl,
              int ldb, int boffz,
              const float* __restrict__ bias, int biasoffz,
              int K,
              float* __restrict__ Cf,
              __nv_bfloat16* __restrict__ Ch, __nv_bfloat16* __restrict__ Cl,
              int ldc, int coffz,
              const float* __restrict__ sarr, const float* __restrict__ bvv)
{
    extern __shared__ char smem[];
    const uint32_t sbuf = smem_u32(smem);
    const int tid = threadIdx.x, wid = tid >> 5, lane = tid & 31;
    const int z = blockIdx.z;
    const int m0 = blockIdx.y * 128, n0 = blockIdx.x * 128;
    const int warp_m = (wid >> 1) * 64;    // 2 warps in M (64 rows each)
    const int warp_n = (wid & 1) * 64;     // 2 warps in N (64 cols each)

    const __nv_bfloat16* Abase_h = Ah + (size_t)m0 * lda + (size_t)z * aoffz;
    const __nv_bfloat16* Abase_l = Al + (size_t)m0 * lda + (size_t)z * aoffz;
    const __nv_bfloat16* Bbase_h = Bh + (size_t)z * boffz + (size_t)n0 * ldb;
    const __nv_bfloat16* Bbase_l = Bl + (size_t)z * boffz + (size_t)n0 * ldb;

    float acc[4][8][4];                    // mt x (np*2+p) x frag
#pragma unroll
    for (int a = 0; a < 4; a++)
#pragma unroll
        for (int b = 0; b < 8; b++)
#pragma unroll
            for (int c = 0; c < 4; c++) acc[a][b][c] = 0.f;

    const int KT = K >> 5;

    auto load_stage = [&](int kt, int s) {
        const uint32_t base = sbuf + s * STAGEB;
        const int k0 = kt << 5;
#pragma unroll
        for (int part = 0; part < 4; part++) {
            const __nv_bfloat16* src =
                (part == 0 ? Abase_h : part == 1 ? Abase_l : part == 2 ? Bbase_h : Bbase_l);
            const int ld = (part < 2) ? lda : ldb;
            const uint32_t dstb = base + part * TILEB;
#pragma unroll
            for (int i = 0; i < 4; i++) {
                int idx = i * 128 + tid;           // 512 granules of 16B
                int row = idx >> 2, g = idx & 3;
                int unit = g ^ ((row >> 1) & 3);
                cpa16(dstb + (uint32_t)(row * 64 + unit * 16),
                      src + (size_t)row * ld + k0 + g * 8);
            }
        }
        CP_COMMIT();
    };

    load_stage(0, 0);
    load_stage(1, 1);

    int s = 0, ls = 2;
    for (int kt = 0; kt < KT; kt++) {
        if (kt == KT - 1) { CP_WAIT0(); } else { CP_WAIT1(); }
        __syncthreads();

        const uint32_t base = sbuf + s * STAGEB;
#pragma unroll
        for (int kk = 0; kk < 2; kk++) {
            // hold all B fragments for this warp's 64 N-cols (resident)
            uint32_t bh[4][4], bl[4][4];
#pragma unroll
            for (int np = 0; np < 4; np++) {
                const uint32_t nrow = warp_n + np * 16 + ((lane >> 4) & 1) * 8 + (lane & 7);
                const uint32_t cu = (kk * 2 + ((lane >> 3) & 1)) ^ ((nrow >> 1) & 3);
                const uint32_t bd = base + 2 * TILEB + nrow * 64 + cu * 16;
                LDSM4(bh[np][0], bh[np][1], bh[np][2], bh[np][3], bd);
                LDSM4(bl[np][0], bl[np][1], bl[np][2], bl[np][3], bd + TILEB);
            }
            // stream A fragments per mt (4 x 16 rows = 64)
#pragma unroll
            for (int mt = 0; mt < 4; mt++) {
                const uint32_t arow = warp_m + mt * 16 + ((lane >> 3) & 1) * 8 + (lane & 7);
                const uint32_t cu = (kk * 2 + (lane >> 4)) ^ ((arow >> 1) & 3);
                const uint32_t ad = base + arow * 64 + cu * 16;
                uint32_t ah[4], al[4];
                LDSM4(ah[0], ah[1], ah[2], ah[3], ad);
                LDSM4(al[0], al[1], al[2], al[3], ad + TILEB);
                // pass 1: Ah x Bh  (8 independent accs)
#pragma unroll
                for (int np = 0; np < 4; np++) {
                    MMA_BF16(acc[mt][np * 2],     ah, bh[np][0], bh[np][1]);
                    MMA_BF16(acc[mt][np * 2 + 1], ah, bh[np][2], bh[np][3]);
                }
                // pass 2: Ah x Bl
#pragma unroll
                for (int np = 0; np < 4; np++) {
                    MMA_BF16(acc[mt][np * 2],     ah, bl[np][0], bl[np][1]);
                    MMA_BF16(acc[mt][np * 2 + 1], ah, bl[np][2], bl[np][3]);
                }
                // pass 3: Al x Bh
#pragma unroll
                for (int np = 0; np < 4; np++) {
                    MMA_BF16(acc[mt][np * 2],     al, bh[np][0], bh[np][1]);
                    MMA_BF16(acc[mt][np * 2 + 1], al, bh[np][2], bh[np][3]);
                }
            }
        }
        // loads AFTER the MMA block (R6 ordering): stage ls was last read at
        // kt-1, which the barrier above orders.
        if (kt + 2 < KT) load_stage(kt + 2, ls);
        s  = (s  == NSTAGE - 1) ? 0 : s + 1;
        ls = (ls == NSTAGE - 1) ? 0 : ls + 1;
    }

    // ------------- epilogue -------------
    const int tr = lane >> 2, tc = (lane & 3) * 2;
#pragma unroll
    for (int mt = 0; mt < 4; mt++) {
#pragma unroll
        for (int half = 0; half < 2; half++) {
            const int r = m0 + warp_m + mt * 16 + tr + half * 8;
            float sv8[NEXP];
            if (EPI == EPI_VSUM) {
#pragma unroll
                for (int n = 0; n < NEXP; n++) sv8[n] = sarr[n * BATCH + r];
            }
#pragma unroll
            for (int j = 0; j < 8; j++) {
                const int col = n0 + warp_n + j * 8 + tc;
                float v0 = acc[mt][j][half * 2];
                float v1 = acc[mt][j][half * 2 + 1];

                if (EPI == EPI_RELU) {
                    v0 += bias[(size_t)z * biasoffz + col];
                    v1 += bias[(size_t)z * biasoffz + col + 1];
                    v0 = fmaxf(v0, 0.f); v1 = fmaxf(v1, 0.f);
                    __nv_bfloat16 h0 = __float2bfloat16_rn(v0);
                    __nv_bfloat16 h1 = __float2bfloat16_rn(v1);
                    __nv_bfloat16 l0 = __float2bfloat16_rn(v0 - __bfloat162float(h0));
                    __nv_bfloat16 l1 = __float2bfloat16_rn(v1 - __bfloat162float(h1));
                    size_t o = (size_t)r * ldc + (size_t)z * coffz + col;
                    *(__nv_bfloat162*)(Ch + o) = __halves2bfloat162(h0, h1);
                    *(__nv_bfloat162*)(Cl + o) = __halves2bfloat162(l0, l1);
                } else if (EPI == EPI_VSUM) {
#pragma unroll
                    for (int n = 0; n < NEXP; n++) {
                        v0 += bvv[n * DVV + col]     * sv8[n];
                        v1 += bvv[n * DVV + col + 1] * sv8[n];
                    }
                    __nv_bfloat16 h0 = __float2bfloat16_rn(v0);
                    __nv_bfloat16 h1 = __float2bfloat16_rn(v1);
                    __nv_bfloat16 l0 = __float2bfloat16_rn(v0 - __bfloat162float(h0));
                    __nv_bfloat16 l1 = __float2bfloat16_rn(v1 - __bfloat162float(h1));
                    size_t o = (size_t)r * ldc + col;
                    *(__nv_bfloat162*)(Ch + o) = __halves2bfloat162(h0, h1);
                    *(__nv_bfloat162*)(Cl + o) = __halves2bfloat162(l0, l1);
                } else {   // EPI_SPLIT
                    v0 += bias[col]; v1 += bias[col + 1];
                    if (col < 64) {
                        Cf[(size_t)r * 64 + col]     = v0;
                        Cf[(size_t)r * 64 + col + 1] = v1;
                    } else {
                        float l0 = fminf(fmaxf(v0, -20.f), 2.f);
                        float l1 = fminf(fmaxf(v1, -20.f), 2.f);
                        Cf[(size_t)BATCH * 64 + (size_t)r * 64 + (col - 64)]     = expf(l0);
                        Cf[(size_t)BATCH * 64 + (size_t)r * 64 + (col - 63)]     = expf(l1);
                        Cf[(size_t)2 * BATCH * 64 + (size_t)r * 64 + (col - 64)] = l0;
                        Cf[(size_t)2 * BATCH * 64 + (size_t)r * 64 + (col - 63)] = l1;
                    }
                }
            }
        }
    }
}

// ------------------------- prep kernels ------------------------------------
__global__ void transpose_split_k(const float* __restrict__ W,
                                  __nv_bfloat16* __restrict__ Th,
                                  __nv_bfloat16* __restrict__ Tl,
                                  int K, int N, int ors, size_t zoff)
{
    __shared__ float tile[32][33];
    const int z = blockIdx.z;
    const float* Wb = W + (size_t)z * K * N;
    const int k0 = blockIdx.x * 32, n0 = blockIdx.y * 32;
    const int tx = threadIdx.x, ty = threadIdx.y;   // 16 x 16
#pragma unroll
    for (int ii = 0; ii < 2; ii++)
#pragma unroll
        for (int jj = 0; jj < 2; jj++)
            tile[ty + 16 * ii][tx + 16 * jj] =
                Wb[(size_t)(k0 + ty + 16 * ii) * N + n0 + tx + 16 * jj];
    __syncthreads();
#pragma unroll
    for (int ii = 0; ii < 2; ii++) {
        const int i = ty + 16 * ii;
        float v0 = tile[tx * 2][i], v1 = tile[tx * 2 + 1][i];
        __nv_bfloat16 h0 = __float2bfloat16_rn(v0);
        __nv_bfloat16 h1 = __float2bfloat16_rn(v1);
        __nv_bfloat16 l0 = __float2bfloat16_rn(v0 - __bfloat162float(h0));
        __nv_bfloat16 l1 = __float2bfloat16_rn(v1 - __bfloat162float(h1));
        size_t o = (size_t)z * zoff + (size_t)(n0 + i) * ors + k0 + tx * 2;
        *(__nv_bfloat162*)(Th + o) = __halves2bfloat162(h0, h1);
        *(__nv_bfloat162*)(Tl + o) = __halves2bfloat162(l0, l1);
    }
}

__global__ void split_k(const float* __restrict__ X, __nv_bfloat16* __restrict__ Xh,
                        __nv_bfloat16* __restrict__ Xl, int n)
{
    int i = (blockIdx.x * 256 + threadIdx.x) * 4;
    if (i < n) {
        float4 v = *(const float4*)(X + i);
        __nv_bfloat16 h0 = __float2bfloat16_rn(v.x), h1 = __float2bfloat16_rn(v.y);
        __nv_bfloat16 h2 = __float2bfloat16_rn(v.z), h3 = __float2bfloat16_rn(v.w);
        __nv_bfloat16 l0 = __float2bfloat16_rn(v.x - __bfloat162float(h0));
        __nv_bfloat16 l1 = __float2bfloat16_rn(v.y - __bfloat162float(h1));
        __nv_bfloat16 l2 = __float2bfloat16_rn(v.z - __bfloat162float(h2));
        __nv_bfloat16 l3 = __float2bfloat16_rn(v.w - __bfloat162float(h3));
        __nv_bfloat162 hp0 = __halves2bfloat162(h0, h1), hp1 = __halves2bfloat162(h2, h3);
        __nv_bfloat162 lp0 = __halves2bfloat162(l0, l1), lp1 = __halves2bfloat162(l2, l3);
        uint2 hu, lu;
        hu.x = *(uint32_t*)&hp0; hu.y = *(uint32_t*)&hp1;
        lu.x = *(uint32_t*)&lp0; lu.y = *(uint32_t*)&lp1;
        *(uint2*)(Xh + i) = hu;
        *(uint2*)(Xl + i) = lu;
    }
}

// q = Wq[t][t,:] + bq[t];  cn[n] = dot(bk[n], q)
__global__ void prep_k(const float* __restrict__ Wq, const float* __restrict__ bq,
                       const float* __restrict__ bk, const int* __restrict__ task_id)
{
    __shared__ float qs[DKK];
    const int t = *task_id;
    const int tid = threadIdx.x;
    float qv = Wq[(size_t)(t * NTASKS + t) * DKK + tid] + bq[(size_t)t * DKK + tid];
    g_q[tid] = qv;
    qs[tid]  = qv;
    __syncthreads();
    const int w = tid >> 5, lane = tid & 31;
    float sum = 0.f;
#pragma unroll
    for (int k = lane; k < DKK; k += 32) sum += bk[(size_t)w * DKK + k] * qs[k];
#pragma unroll
    for (int o = 16; o; o >>= 1) sum += __shfl_xor_sync(0xffffffffu, sum, o);
    if (lane == 0) g_cn[w] = sum;
}

// wn[i] = dot(Wk[i,:], q)
__global__ void wn_k(const float* __restrict__ Wk)
{
    const int tid = threadIdx.x, w = tid >> 5, lane = tid & 31;
    const int row = blockIdx.x * 8 + w;
    const float* wr = Wk + (size_t)row * DKK;
    float sum = 0.f;
#pragma unroll
    for (int k = lane; k < DKK; k += 32) sum += wr[k] * g_q[k];
#pragma unroll
    for (int o = 16; o; o >>= 1) sum += __shfl_xor_sync(0xffffffffu, sum, o);
    if (lane == 0) g_wn[row] = sum;
}

// fused: s[n][b] = dot(e2[b, n*DH..], wn[n]) + cn[n], then
// vt[b, n*DH+d] = split(e2[b,n*DH+d] * s[n][b]).
__global__ void expkq_scale_k()
{
    __shared__ uint32_t shh[8][512], shl[8][512];
    const int tid = threadIdx.x, w = tid >> 5, lane = tid & 31;
    const int row = blockIdx.x * 8 + w;
    const int n = blockIdx.y;
    const size_t base = (size_t)row * NDH8 + (size_t)n * DH;
    const float* wn = g_wn + n * DH;
    float sum = 0.f;
#pragma unroll 4
    for (int it = 0; it < 16; it++) {
        const int k2 = it * 32 + lane;
        uint32_t h2 = *(const uint32_t*)(g_e2h + base + k2 * 2);
        uint32_t l2 = *(const uint32_t*)(g_e2l + base + k2 * 2);
        shh[w][k2] = h2; shl[w][k2] = l2;
        __nv_bfloat162 hb = *(__nv_bfloat162*)&h2;
        __nv_bfloat162 lb = *(__nv_bfloat162*)&l2;
        float2 wv = *(const float2*)(wn + k2 * 2);
        sum += (__bfloat162float(hb.x) + __bfloat162float(lb.x)) * wv.x
             + (__bfloat162float(hb.y) + __bfloat162float(lb.y)) * wv.y;
    }
#pragma unroll
    for (int o = 16; o; o >>= 1) sum += __shfl_xor_sync(0xffffffffu, sum, o);
    const float s = sum + g_cn[n];
    if (lane == 0) g_s[n * BATCH + row] = s;
#pragma unroll 4
    for (int it = 0; it < 16; it++) {
        const int k2 = it * 32 + lane;
        uint32_t h2 = shh[w][k2], l2 = shl[w][k2];
        __nv_bfloat162 hb = *(__nv_bfloat162*)&h2;
        __nv_bfloat162 lb = *(__nv_bfloat162*)&l2;
        float v0 = (__bfloat162float(hb.x) + __bfloat162float(lb.x)) * s;
        float v1 = (__bfloat162float(hb.y) + __bfloat162float(lb.y)) * s;
        __nv_bfloat16 hh0 = __float2bfloat16_rn(v0), hh1 = __float2bfloat16_rn(v1);
        __nv_bfloat16 ll0 = __float2bfloat16_rn(v0 - __bfloat162float(hh0));
        __nv_bfloat16 ll1 = __float2bfloat16_rn(v1 - __bfloat162float(hh1));
        *(__nv_bfloat162*)(g_vth + base + k2 * 2) = __halves2bfloat162(hh0, hh1);
        *(__nv_bfloat162*)(g_vtl + base + k2 * 2) = __halves2bfloat162(ll0, ll1);
    }
}

// ------------------------- launch ------------------------------------------
extern "C" void kernel_launch(void* const* d_in, const int* in_sizes, int n_in,
                              void* d_out, int out_size)
{
    const float* x    = (const float*)d_in[0];
    const int*   task = (const int*)  d_in[1];
    const float* Wb1  = (const float*)d_in[2];
    const float* bb1  = (const float*)d_in[3];
    const float* Wb2  = (const float*)d_in[4];
    const float* bb2  = (const float*)d_in[5];
    const float* We1  = (const float*)d_in[6];
    const float* be1  = (const float*)d_in[7];
    const float* We2  = (const float*)d_in[8];
    const float* be2  = (const float*)d_in[9];
    const float* Wv   = (const float*)d_in[10];
    const float* bv   = (const float*)d_in[11];
    const float* Wk   = (const float*)d_in[12];
    const float* bk   = (const float*)d_in[13];
    const float* Wq   = (const float*)d_in[14];
    const float* bq   = (const float*)d_in[15];
    const float* Wt1  = (const float*)d_in[16];
    const float* bt1  = (const float*)d_in[17];
    const float* Wl   = (const float*)d_in[18];
    const float* bl   = (const float*)d_in[19];
    float* out = (float*)d_out;

#define SYM(p, s) do { void* _t; cudaGetSymbolAddress(&_t, s); p = (decltype(p))_t; } while (0)
    __nv_bfloat16 *xh, *xl, *h1h, *h1l, *hh, *hl, *e1h, *e1l, *e2h, *e2l;
    __nv_bfloat16 *vth, *vtl, *rh, *rl, *th, *tl;
    __nv_bfloat16 *Wb1h, *Wb1l, *Wb2h, *Wb2l, *We1h, *We1l, *We2h, *We2l;
    __nv_bfloat16 *Wvh, *Wvl, *Wt1h, *Wt1l, *Wlh, *Wll;
    float *sc;
    SYM(xh, g_xh);  SYM(xl, g_xl);  SYM(h1h, g_h1h); SYM(h1l, g_h1l);
    SYM(hh, g_hh);  SYM(hl, g_hl);  SYM(e1h, g_e1h); SYM(e1l, g_e1l);
    SYM(e2h, g_e2h); SYM(e2l, g_e2l); SYM(vth, g_vth); SYM(vtl, g_vtl);
    SYM(rh, g_rh);  SYM(rl, g_rl);  SYM(th, g_th);  SYM(tl, g_tl);
    SYM(Wb1h, g_Wb1h); SYM(Wb1l, g_Wb1l); SYM(Wb2h, g_Wb2h); SYM(Wb2l, g_Wb2l);
    SYM(We1h, g_We1h); SYM(We1l, g_We1l); SYM(We2h, g_We2h); SYM(We2l, g_We2l);
    SYM(Wvh, g_Wvh); SYM(Wvl, g_Wvl); SYM(Wt1h, g_Wt1h); SYM(Wt1l, g_Wt1l);
    SYM(Wlh, g_Wlh); SYM(Wll, g_Wll); SYM(sc, g_s);

    cudaFuncSetAttribute(mma_gemm<EPI_RELU >, cudaFuncAttributeMaxDynamicSharedMemorySize, SMEMSZ);
    cudaFuncSetAttribute(mma_gemm<EPI_VSUM >, cudaFuncAttributeMaxDynamicSharedMemorySize, SMEMSZ);
    cudaFuncSetAttribute(mma_gemm<EPI_SPLIT>, cudaFuncAttributeMaxDynamicSharedMemorySize, SMEMSZ);

    dim3 tb(16, 16);

    split_k<<<(BATCH * OBSD / 4 + 255) / 256, 256>>>(x, xh, xl, BATCH * OBSD);                  // 0
    transpose_split_k<<<dim3(OBSD / 32, DH / 32, 1),  tb>>>(Wb1, Wb1h, Wb1l, OBSD, DH, OBSD, 0); // 1
    transpose_split_k<<<dim3(DH / 32, DH / 32, 1),    tb>>>(Wb2, Wb2h, Wb2l, DH, DH, DH, 0);     // 2
    mma_gemm<EPI_RELU><<<dim3(8, 32), 128, SMEMSZ>>>(                                            // 3: base1
        xh, xl, OBSD, 0, Wb1h, Wb1l, OBSD, 0, bb1, 0, OBSD,
        nullptr, h1h, h1l, DH, 0, nullptr, nullptr);
    transpose_split_k<<<dim3(DH / 32, DH / 32, NEXP), tb>>>(We1, We1h, We1l, DH, DH, DH, (size_t)DH * DH); // 4
    mma_gemm<EPI_RELU><<<dim3(8, 32), 128, SMEMSZ>>>(                                            // 5: base2
        h1h, h1l, DH, 0, Wb2h, Wb2l, DH, 0, bb2, 0, DH,
        nullptr, hh, hl, DH, 0, nullptr, nullptr);
    transpose_split_k<<<dim3(DH / 32, DH / 32, NEXP), tb>>>(We2, We2h, We2l, DH, DH, DH, (size_t)DH * DH); // 6

    // all experts e1: one GEMM, N = 8192
    mma_gemm<EPI_RELU><<<dim3(NDH8 / 128, 32), 128, SMEMSZ>>>(                                   // 7
        hh, hl, DH, 0, We1h, We1l, DH, 0, be1, 0, DH,
        nullptr, e1h, e1l, NDH8, 0, nullptr, nullptr);

    // all experts e2: z-batched block-diagonal GEMM
    mma_gemm<EPI_RELU><<<dim3(DH / 128, 32, NEXP), 128, SMEMSZ>>>(                               // 8
        e1h, e1l, NDH8, DH, We2h, We2l, DH, DH * DH, be2, DH, DH,
        nullptr, e2h, e2l, NDH8, DH, nullptr, nullptr);

    prep_k<<<1, 256>>>(Wq, bq, bk, task);                                                        // 9
    wn_k<<<NEXP * DH / 8, 256>>>(Wk);                                                            // 10
    expkq_scale_k<<<dim3(BATCH / 8, NEXP), 256>>>();                                             // 11

    transpose_split_k<<<dim3(DH / 32, DVV / 32, NEXP), tb>>>(Wv, Wvh, Wvl, DH, DVV, NDH8, (size_t)DH); // 12

    // fused v-sum: single GEMM over K = 8192
    mma_gemm<EPI_VSUM><<<dim3(DVV / 128, 32), 128, SMEMSZ>>>(                                    // 13
        vth, vtl, NDH8, 0, Wvh, Wvl, NDH8, 0, nullptr, 0, NDH8,
        nullptr, rh, rl, DVV, 0, sc, bv);

    transpose_split_k<<<dim3(DVV / 32, DH / 32, 1), tb>>>(Wt1, Wt1h, Wt1l, DVV, DH, DVV, 0);     // 14
    mma_gemm<EPI_RELU><<<dim3(DH / 128, 32), 128, SMEMSZ>>>(                                     // 15
        rh, rl, DVV, 0, Wt1h, Wt1l, DVV, 0, bt1, 0, DVV,
        nullptr, th, tl, DH, 0, nullptr, nullptr);

    transpose_split_k<<<dim3(DH / 32, NOUT / 32, 1), tb>>>(Wl, Wlh, Wll, DH, NOUT, DH, 0);       // 16
    mma_gemm<EPI_SPLIT><<<dim3(1, 32), 128, SMEMSZ>>>(                                           // 17
        th, tl, DH, 0, Wlh, Wll, DH, 0, bl, 0, DH,
        out, nullptr, nullptr, NOUT, 0, nullptr, nullptr);
}

// round 9
// speedup vs baseline: 1.0906x; 1.0018x over previous
#include <cuda_runtime.h>
#include <cuda_bf16.h>
#include <math.h>
#include <stdint.h>

#define BATCH  4096
#define OBSD   512
#define DH     1024
#define NEXP   8
#define DKK    256
#define DVV    1024
#define NTASKS 10
#define NOUT   128
#define NDH8   (NEXP * DH)          // 8192

// ------------------------- scratch (device globals) ------------------------
__device__ __nv_bfloat16 g_xh [BATCH*OBSD], g_xl [BATCH*OBSD];
__device__ __nv_bfloat16 g_h1h[BATCH*DH],   g_h1l[BATCH*DH];
__device__ __nv_bfloat16 g_hh [BATCH*DH],   g_hl [BATCH*DH];
__device__ __nv_bfloat16 g_e1h[(size_t)BATCH*NDH8], g_e1l[(size_t)BATCH*NDH8];
__device__ __nv_bfloat16 g_e2h[(size_t)BATCH*NDH8], g_e2l[(size_t)BATCH*NDH8];
__device__ __nv_bfloat16 g_vth[(size_t)BATCH*NDH8], g_vtl[(size_t)BATCH*NDH8];
__device__ __nv_bfloat16 g_rh [BATCH*DVV],  g_rl [BATCH*DVV];
__device__ __nv_bfloat16 g_th [BATCH*DH],   g_tl [BATCH*DH];

__device__ __nv_bfloat16 g_Wb1h[DH*OBSD],     g_Wb1l[DH*OBSD];
__device__ __nv_bfloat16 g_Wb2h[DH*DH],       g_Wb2l[DH*DH];
__device__ __nv_bfloat16 g_We1h[NEXP*DH*DH],  g_We1l[NEXP*DH*DH];
__device__ __nv_bfloat16 g_We2h[NEXP*DH*DH],  g_We2l[NEXP*DH*DH];
__device__ __nv_bfloat16 g_Wvh [(size_t)DVV*NDH8], g_Wvl [(size_t)DVV*NDH8];
__device__ __nv_bfloat16 g_Wt1h[DH*DVV],      g_Wt1l[DH*DVV];
__device__ __nv_bfloat16 g_Wlh [NOUT*DH],     g_Wll [NOUT*DH];

__device__ float g_q[DKK], g_wn[NEXP*DH], g_cn[NEXP], g_s[NEXP*BATCH];

// ------------------------- PTX helpers -------------------------------------
__device__ __forceinline__ uint32_t smem_u32(const void* p) {
    uint32_t a;
    asm("{ .reg .u64 t; cvta.to.shared.u64 t, %1; cvt.u32.u64 %0, t; }" : "=r"(a) : "l"(p));
    return a;
}
__device__ __forceinline__ void cpa16(uint32_t dst, const void* src) {
    asm volatile("cp.async.cg.shared.global [%0], [%1], 16;" :: "r"(dst), "l"(src));
}
#define CP_COMMIT() asm volatile("cp.async.commit_group;" ::: "memory")
#define CP_WAIT0()  asm volatile("cp.async.wait_group 0;" ::: "memory")
#define CP_WAIT1()  asm volatile("cp.async.wait_group 1;" ::: "memory")

#define LDSM4(r0, r1, r2, r3, addr) \
    asm volatile("ldmatrix.sync.aligned.m8n8.x4.shared.b16 {%0,%1,%2,%3}, [%4];" \
                 : "=r"(r0), "=r"(r1), "=r"(r2), "=r"(r3) : "r"(addr))

#define MMA_BF16(d, a, b0v, b1v) \
    asm volatile("mma.sync.aligned.m16n8k16.row.col.f32.bf16.bf16.f32 " \
                 "{%0,%1,%2,%3},{%4,%5,%6,%7},{%8,%9},{%0,%1,%2,%3};" \
                 : "+f"((d)[0]), "+f"((d)[1]), "+f"((d)[2]), "+f"((d)[3]) \
                 : "r"((a)[0]), "r"((a)[1]), "r"((a)[2]), "r"((a)[3]), \
                   "r"(b0v), "r"(b1v))

// ------------------------- mma.sync bf16x3 GEMM -----------------------------
// CTA tile 128x128, 128 threads (4 warps, 2x2 grid of 64x64 warp tiles).
// Pad-free XOR swizzle: 128 rows x 32 bf16 cols = 64B/row; 16B unit index
// swizzled as  unit' = unit ^ ((row>>1)&3).
enum { EPI_RELU = 0, EPI_VSUM = 1, EPI_SPLIT = 2 };

#define TILEB  8192                       // 128 * 64B
#define STAGEB (4 * TILEB)                // Ah,Al,Bh,Bl = 32 KB
#define NSTAGE 3
#define SMEMSZ (NSTAGE * STAGEB)          // 98304

template <int EPI>
__global__ __launch_bounds__(128, 2)
void mma_gemm(const __nv_bfloat16* __restrict__ Ah, const __nv_bfloat16* __restrict__ Al,
              int lda, int aoffz,
              const __nv_bfloat16* __restrict__ Bh, const __nv_bfloat16* __restrict__ Bl,
              int ldb, int boffz,
              const float* __restrict__ bias, int biasoffz,
              int K,
              float* __restrict__ Cf,
              __nv_bfloat16* __restrict__ Ch, __nv_bfloat16* __restrict__ Cl,
              int ldc, int coffz,
              const float* __restrict__ sarr, const float* __restrict__ bvv)
{
    extern __shared__ char smem[];
    const uint32_t sbuf = smem_u32(smem);
    const int tid = threadIdx.x, wid = tid >> 5, lane = tid & 31;
    const int z = blockIdx.z;
    const int m0 = blockIdx.y * 128, n0 = blockIdx.x * 128;
    const int warp_m = (wid >> 1) * 64;    // 2 warps in M (64 rows each)
    const int warp_n = (wid & 1) * 64;     // 2 warps in N (64 cols each)

    const __nv_bfloat16* Abase_h = Ah + (size_t)m0 * lda + (size_t)z * aoffz;
    const __nv_bfloat16* Abase_l = Al + (size_t)m0 * lda + (size_t)z * aoffz;
    const __nv_bfloat16* Bbase_h = Bh + (size_t)z * boffz + (size_t)n0 * ldb;
    const __nv_bfloat16* Bbase_l = Bl + (size_t)z * boffz + (size_t)n0 * ldb;

    float acc[4][8][4];                    // mt x (np*2+p) x frag
#pragma unroll
    for (int a = 0; a < 4; a++)
#pragma unroll
        for (int b = 0; b < 8; b++)
#pragma unroll
            for (int c = 0; c < 4; c++) acc[a][b][c] = 0.f;

    const int KT = K >> 5;

    auto load_stage = [&](int kt, int s) {
        const uint32_t base = sbuf + s * STAGEB;
        const int k0 = kt << 5;
#pragma unroll
        for (int part = 0; part < 4; part++) {
            const __nv_bfloat16* src =
                (part == 0 ? Abase_h : part == 1 ? Abase_l : part == 2 ? Bbase_h : Bbase_l);
            const int ld = (part < 2) ? lda : ldb;
            const uint32_t dstb = base + part * TILEB;
#pragma unroll
            for (int i = 0; i < 4; i++) {
                int idx = i * 128 + tid;           // 512 granules of 16B
                int row = idx >> 2, g = idx & 3;
                int unit = g ^ ((row >> 1) & 3);
                cpa16(dstb + (uint32_t)(row * 64 + unit * 16),
                      src + (size_t)row * ld + k0 + g * 8);
            }
        }
        CP_COMMIT();
    };

    // per-mt A fragment address helper
    auto a_addr = [&](uint32_t base, int kk, int mt) -> uint32_t {
        const uint32_t arow = warp_m + mt * 16 + ((lane >> 3) & 1) * 8 + (lane & 7);
        const uint32_t cu = (kk * 2 + (lane >> 4)) ^ ((arow >> 1) & 3);
        return base + arow * 64 + cu * 16;
    };

    load_stage(0, 0);
    load_stage(1, 1);

    int s = 0, ls = 2;
    for (int kt = 0; kt < KT; kt++) {
        if (kt == KT - 1) { CP_WAIT0(); } else { CP_WAIT1(); }
        __syncthreads();

        const uint32_t base = sbuf + s * STAGEB;
#pragma unroll
        for (int kk = 0; kk < 2; kk++) {
            // B-hi first (gates pass 1), then A[0], then B-lo (hidden by pass 1)
            uint32_t bh[4][4], bl[4][4];
            uint32_t bdv[4];
#pragma unroll
            for (int np = 0; np < 4; np++) {
                const uint32_t nrow = warp_n + np * 16 + ((lane >> 4) & 1) * 8 + (lane & 7);
                const uint32_t cu = (kk * 2 + ((lane >> 3) & 1)) ^ ((nrow >> 1) & 3);
                bdv[np] = base + 2 * TILEB + nrow * 64 + cu * 16;
                LDSM4(bh[np][0], bh[np][1], bh[np][2], bh[np][3], bdv[np]);
            }
            uint32_t ah[2][4], al[2][4];
            {
                const uint32_t ad = a_addr(base, kk, 0);
                LDSM4(ah[0][0], ah[0][1], ah[0][2], ah[0][3], ad);
                LDSM4(al[0][0], al[0][1], al[0][2], al[0][3], ad + TILEB);
            }
#pragma unroll
            for (int np = 0; np < 4; np++)
                LDSM4(bl[np][0], bl[np][1], bl[np][2], bl[np][3], bdv[np] + TILEB);

#pragma unroll
            for (int mt = 0; mt < 4; mt++) {
                const int cur = mt & 1, nxt = cur ^ 1;
                if (mt < 3) {                      // prefetch A[mt+1]
                    const uint32_t ad = a_addr(base, kk, mt + 1);
                    LDSM4(ah[nxt][0], ah[nxt][1], ah[nxt][2], ah[nxt][3], ad);
                    LDSM4(al[nxt][0], al[nxt][1], al[nxt][2], al[nxt][3], ad + TILEB);
                }
                // pass 1: Ah x Bh  (8 independent accs)
#pragma unroll
                for (int np = 0; np < 4; np++) {
                    MMA_BF16(acc[mt][np * 2],     ah[cur], bh[np][0], bh[np][1]);
                    MMA_BF16(acc[mt][np * 2 + 1], ah[cur], bh[np][2], bh[np][3]);
                }
                // pass 2: Ah x Bl
#pragma unroll
                for (int np = 0; np < 4; np++) {
                    MMA_BF16(acc[mt][np * 2],     ah[cur], bl[np][0], bl[np][1]);
                    MMA_BF16(acc[mt][np * 2 + 1], ah[cur], bl[np][2], bl[np][3]);
                }
                // pass 3: Al x Bh
#pragma unroll
                for (int np = 0; np < 4; np++) {
                    MMA_BF16(acc[mt][np * 2],     al[cur], bh[np][0], bh[np][1]);
                    MMA_BF16(acc[mt][np * 2 + 1], al[cur], bh[np][2], bh[np][3]);
                }
            }
        }
        // loads AFTER the MMA block (R6 ordering)
        if (kt + 2 < KT) load_stage(kt + 2, ls);
        s  = (s  == NSTAGE - 1) ? 0 : s + 1;
        ls = (ls == NSTAGE - 1) ? 0 : ls + 1;
    }

    // ------------- epilogue -------------
    const int tr = lane >> 2, tc = (lane & 3) * 2;
#pragma unroll
    for (int mt = 0; mt < 4; mt++) {
#pragma unroll
        for (int half = 0; half < 2; half++) {
            const int r = m0 + warp_m + mt * 16 + tr + half * 8;
            float sv8[NEXP];
            if (EPI == EPI_VSUM) {
#pragma unroll
                for (int n = 0; n < NEXP; n++) sv8[n] = sarr[n * BATCH + r];
            }
#pragma unroll
            for (int j = 0; j < 8; j++) {
                const int col = n0 + warp_n + j * 8 + tc;
                float v0 = acc[mt][j][half * 2];
                float v1 = acc[mt][j][half * 2 + 1];

                if (EPI == EPI_RELU) {
                    v0 += bias[(size_t)z * biasoffz + col];
                    v1 += bias[(size_t)z * biasoffz + col + 1];
                    v0 = fmaxf(v0, 0.f); v1 = fmaxf(v1, 0.f);
                    __nv_bfloat16 h0 = __float2bfloat16_rn(v0);
                    __nv_bfloat16 h1 = __float2bfloat16_rn(v1);
                    __nv_bfloat16 l0 = __float2bfloat16_rn(v0 - __bfloat162float(h0));
                    __nv_bfloat16 l1 = __float2bfloat16_rn(v1 - __bfloat162float(h1));
                    size_t o = (size_t)r * ldc + (size_t)z * coffz + col;
                    *(__nv_bfloat162*)(Ch + o) = __halves2bfloat162(h0, h1);
                    *(__nv_bfloat162*)(Cl + o) = __halves2bfloat162(l0, l1);
                } else if (EPI == EPI_VSUM) {
#pragma unroll
                    for (int n = 0; n < NEXP; n++) {
                        v0 += bvv[n * DVV + col]     * sv8[n];
                        v1 += bvv[n * DVV + col + 1] * sv8[n];
                    }
                    __nv_bfloat16 h0 = __float2bfloat16_rn(v0);
                    __nv_bfloat16 h1 = __float2bfloat16_rn(v1);
                    __nv_bfloat16 l0 = __float2bfloat16_rn(v0 - __bfloat162float(h0));
                    __nv_bfloat16 l1 = __float2bfloat16_rn(v1 - __bfloat162float(h1));
                    size_t o = (size_t)r * ldc + col;
                    *(__nv_bfloat162*)(Ch + o) = __halves2bfloat162(h0, h1);
                    *(__nv_bfloat162*)(Cl + o) = __halves2bfloat162(l0, l1);
                } else {   // EPI_SPLIT
                    v0 += bias[col]; v1 += bias[col + 1];
                    if (col < 64) {
                        Cf[(size_t)r * 64 + col]     = v0;
                        Cf[(size_t)r * 64 + col + 1] = v1;
                    } else {
                        float l0 = fminf(fmaxf(v0, -20.f), 2.f);
                        float l1 = fminf(fmaxf(v1, -20.f), 2.f);
                        Cf[(size_t)BATCH * 64 + (size_t)r * 64 + (col - 64)]     = expf(l0);
                        Cf[(size_t)BATCH * 64 + (size_t)r * 64 + (col - 63)]     = expf(l1);
                        Cf[(size_t)2 * BATCH * 64 + (size_t)r * 64 + (col - 64)] = l0;
                        Cf[(size_t)2 * BATCH * 64 + (size_t)r * 64 + (col - 63)] = l1;
                    }
                }
            }
        }
    }
}

// ------------------------- prep kernels ------------------------------------
__global__ void transpose_split_k(const float* __restrict__ W,
                                  __nv_bfloat16* __restrict__ Th,
                                  __nv_bfloat16* __restrict__ Tl,
                                  int K, int N, int ors, size_t zoff)
{
    __shared__ float tile[32][33];
    const int z = blockIdx.z;
    const float* Wb = W + (size_t)z * K * N;
    const int k0 = blockIdx.x * 32, n0 = blockIdx.y * 32;
    const int tx = threadIdx.x, ty = threadIdx.y;   // 16 x 16
#pragma unroll
    for (int ii = 0; ii < 2; ii++)
#pragma unroll
        for (int jj = 0; jj < 2; jj++)
            tile[ty + 16 * ii][tx + 16 * jj] =
                Wb[(size_t)(k0 + ty + 16 * ii) * N + n0 + tx + 16 * jj];
    __syncthreads();
#pragma unroll
    for (int ii = 0; ii < 2; ii++) {
        const int i = ty + 16 * ii;
        float v0 = tile[tx * 2][i], v1 = tile[tx * 2 + 1][i];
        __nv_bfloat16 h0 = __float2bfloat16_rn(v0);
        __nv_bfloat16 h1 = __float2bfloat16_rn(v1);
        __nv_bfloat16 l0 = __float2bfloat16_rn(v0 - __bfloat162float(h0));
        __nv_bfloat16 l1 = __float2bfloat16_rn(v1 - __bfloat162float(h1));
        size_t o = (size_t)z * zoff + (size_t)(n0 + i) * ors + k0 + tx * 2;
        *(__nv_bfloat162*)(Th + o) = __halves2bfloat162(h0, h1);
        *(__nv_bfloat162*)(Tl + o) = __halves2bfloat162(l0, l1);
    }
}

__global__ void split_k(const float* __restrict__ X, __nv_bfloat16* __restrict__ Xh,
                        __nv_bfloat16* __restrict__ Xl, int n)
{
    int i = (blockIdx.x * 256 + threadIdx.x) * 4;
    if (i < n) {
        float4 v = *(const float4*)(X + i);
        __nv_bfloat16 h0 = __float2bfloat16_rn(v.x), h1 = __float2bfloat16_rn(v.y);
        __nv_bfloat16 h2 = __float2bfloat16_rn(v.z), h3 = __float2bfloat16_rn(v.w);
        __nv_bfloat16 l0 = __float2bfloat16_rn(v.x - __bfloat162float(h0));
        __nv_bfloat16 l1 = __float2bfloat16_rn(v.y - __bfloat162float(h1));
        __nv_bfloat16 l2 = __float2bfloat16_rn(v.z - __bfloat162float(h2));
        __nv_bfloat16 l3 = __float2bfloat16_rn(v.w - __bfloat162float(h3));
        __nv_bfloat162 hp0 = __halves2bfloat162(h0, h1), hp1 = __halves2bfloat162(h2, h3);
        __nv_bfloat162 lp0 = __halves2bfloat162(l0, l1), lp1 = __halves2bfloat162(l2, l3);
        uint2 hu, lu;
        hu.x = *(uint32_t*)&hp0; hu.y = *(uint32_t*)&hp1;
        lu.x = *(uint32_t*)&lp0; lu.y = *(uint32_t*)&lp1;
        *(uint2*)(Xh + i) = hu;
        *(uint2*)(Xl + i) = lu;
    }
}

// q = Wq[t][t,:] + bq[t];  cn[n] = dot(bk[n], q)
__global__ void prep_k(const float* __restrict__ Wq, const float* __restrict__ bq,
                       const float* __restrict__ bk, const int* __restrict__ task_id)
{
    __shared__ float qs[DKK];
    const int t = *task_id;
    const int tid = threadIdx.x;
    float qv = Wq[(size_t)(t * NTASKS + t) * DKK + tid] + bq[(size_t)t * DKK + tid];
    g_q[tid] = qv;
    qs[tid]  = qv;
    __syncthreads();
    const int w = tid >> 5, lane = tid & 31;
    float sum = 0.f;
#pragma unroll
    for (int k = lane; k < DKK; k += 32) sum += bk[(size_t)w * DKK + k] * qs[k];
#pragma unroll
    for (int o = 16; o; o >>= 1) sum += __shfl_xor_sync(0xffffffffu, sum, o);
    if (lane == 0) g_cn[w] = sum;
}

// wn[i] = dot(Wk[i,:], q)
__global__ void wn_k(const float* __restrict__ Wk)
{
    const int tid = threadIdx.x, w = tid >> 5, lane = tid & 31;
    const int row = blockIdx.x * 8 + w;
    const float* wr = Wk + (size_t)row * DKK;
    float sum = 0.f;
#pragma unroll
    for (int k = lane; k < DKK; k += 32) sum += wr[k] * g_q[k];
#pragma unroll
    for (int o = 16; o; o >>= 1) sum += __shfl_xor_sync(0xffffffffu, sum, o);
    if (lane == 0) g_wn[row] = sum;
}

// fused: s[n][b] = dot(e2[b, n*DH..], wn[n]) + cn[n], then
// vt[b, n*DH+d] = split(e2[b,n*DH+d] * s[n][b]).
__global__ void expkq_scale_k()
{
    __shared__ uint32_t shh[8][512], shl[8][512];
    const int tid = threadIdx.x, w = tid >> 5, lane = tid & 31;
    const int row = blockIdx.x * 8 + w;
    const int n = blockIdx.y;
    const size_t base = (size_t)row * NDH8 + (size_t)n * DH;
    const float* wn = g_wn + n * DH;
    float sum = 0.f;
#pragma unroll 4
    for (int it = 0; it < 16; it++) {
        const int k2 = it * 32 + lane;
        uint32_t h2 = *(const uint32_t*)(g_e2h + base + k2 * 2);
        uint32_t l2 = *(const uint32_t*)(g_e2l + base + k2 * 2);
        shh[w][k2] = h2; shl[w][k2] = l2;
        __nv_bfloat162 hb = *(__nv_bfloat162*)&h2;
        __nv_bfloat162 lb = *(__nv_bfloat162*)&l2;
        float2 wv = *(const float2*)(wn + k2 * 2);
        sum += (__bfloat162float(hb.x) + __bfloat162float(lb.x)) * wv.x
             + (__bfloat162float(hb.y) + __bfloat162float(lb.y)) * wv.y;
    }
#pragma unroll
    for (int o = 16; o; o >>= 1) sum += __shfl_xor_sync(0xffffffffu, sum, o);
    const float s = sum + g_cn[n];
    if (lane == 0) g_s[n * BATCH + row] = s;
#pragma unroll 4
    for (int it = 0; it < 16; it++) {
        const int k2 = it * 32 + lane;
        uint32_t h2 = shh[w][k2], l2 = shl[w][k2];
        __nv_bfloat162 hb = *(__nv_bfloat162*)&h2;
        __nv_bfloat162 lb = *(__nv_bfloat162*)&l2;
        float v0 = (__bfloat162float(hb.x) + __bfloat162float(lb.x)) * s;
        float v1 = (__bfloat162float(hb.y) + __bfloat162float(lb.y)) * s;
        __nv_bfloat16 hh0 = __float2bfloat16_rn(v0), hh1 = __float2bfloat16_rn(v1);
        __nv_bfloat16 ll0 = __float2bfloat16_rn(v0 - __bfloat162float(hh0));
        __nv_bfloat16 ll1 = __float2bfloat16_rn(v1 - __bfloat162float(hh1));
        *(__nv_bfloat162*)(g_vth + base + k2 * 2) = __halves2bfloat162(hh0, hh1);
        *(__nv_bfloat162*)(g_vtl + base + k2 * 2) = __halves2bfloat162(ll0, ll1);
    }
}

// ------------------------- launch ------------------------------------------
extern "C" void kernel_launch(void* const* d_in, const int* in_sizes, int n_in,
                              void* d_out, int out_size)
{
    const float* x    = (const float*)d_in[0];
    const int*   task = (const int*)  d_in[1];
    const float* Wb1  = (const float*)d_in[2];
    const float* bb1  = (const float*)d_in[3];
    const float* Wb2  = (const float*)d_in[4];
    const float* bb2  = (const float*)d_in[5];
    const float* We1  = (const float*)d_in[6];
    const float* be1  = (const float*)d_in[7];
    const float* We2  = (const float*)d_in[8];
    const float* be2  = (const float*)d_in[9];
    const float* Wv   = (const float*)d_in[10];
    const float* bv   = (const float*)d_in[11];
    const float* Wk   = (const float*)d_in[12];
    const float* bk   = (const float*)d_in[13];
    const float* Wq   = (const float*)d_in[14];
    const float* bq   = (const float*)d_in[15];
    const float* Wt1  = (const float*)d_in[16];
    const float* bt1  = (const float*)d_in[17];
    const float* Wl   = (const float*)d_in[18];
    const float* bl   = (const float*)d_in[19];
    float* out = (float*)d_out;

#define SYM(p, s) do { void* _t; cudaGetSymbolAddress(&_t, s); p = (decltype(p))_t; } while (0)
    __nv_bfloat16 *xh, *xl, *h1h, *h1l, *hh, *hl, *e1h, *e1l, *e2h, *e2l;
    __nv_bfloat16 *vth, *vtl, *rh, *rl, *th, *tl;
    __nv_bfloat16 *Wb1h, *Wb1l, *Wb2h, *Wb2l, *We1h, *We1l, *We2h, *We2l;
    __nv_bfloat16 *Wvh, *Wvl, *Wt1h, *Wt1l, *Wlh, *Wll;
    float *sc;
    SYM(xh, g_xh);  SYM(xl, g_xl);  SYM(h1h, g_h1h); SYM(h1l, g_h1l);
    SYM(hh, g_hh);  SYM(hl, g_hl);  SYM(e1h, g_e1h); SYM(e1l, g_e1l);
    SYM(e2h, g_e2h); SYM(e2l, g_e2l); SYM(vth, g_vth); SYM(vtl, g_vtl);
    SYM(rh, g_rh);  SYM(rl, g_rl);  SYM(th, g_th);  SYM(tl, g_tl);
    SYM(Wb1h, g_Wb1h); SYM(Wb1l, g_Wb1l); SYM(Wb2h, g_Wb2h); SYM(Wb2l, g_Wb2l);
    SYM(We1h, g_We1h); SYM(We1l, g_We1l); SYM(We2h, g_We2h); SYM(We2l, g_We2l);
    SYM(Wvh, g_Wvh); SYM(Wvl, g_Wvl); SYM(Wt1h, g_Wt1h); SYM(Wt1l, g_Wt1l);
    SYM(Wlh, g_Wlh); SYM(Wll, g_Wll); SYM(sc, g_s);

    cudaFuncSetAttribute(mma_gemm<EPI_RELU >, cudaFuncAttributeMaxDynamicSharedMemorySize, SMEMSZ);
    cudaFuncSetAttribute(mma_gemm<EPI_VSUM >, cudaFuncAttributeMaxDynamicSharedMemorySize, SMEMSZ);
    cudaFuncSetAttribute(mma_gemm<EPI_SPLIT>, cudaFuncAttributeMaxDynamicSharedMemorySize, SMEMSZ);

    dim3 tb(16, 16);

    split_k<<<(BATCH * OBSD / 4 + 255) / 256, 256>>>(x, xh, xl, BATCH * OBSD);                  // 0
    transpose_split_k<<<dim3(OBSD / 32, DH / 32, 1),  tb>>>(Wb1, Wb1h, Wb1l, OBSD, DH, OBSD, 0); // 1
    transpose_split_k<<<dim3(DH / 32, DH / 32, 1),    tb>>>(Wb2, Wb2h, Wb2l, DH, DH, DH, 0);     // 2
    mma_gemm<EPI_RELU><<<dim3(8, 32), 128, SMEMSZ>>>(                                            // 3: base1
        xh, xl, OBSD, 0, Wb1h, Wb1l, OBSD, 0, bb1, 0, OBSD,
        nullptr, h1h, h1l, DH, 0, nullptr, nullptr);
    transpose_split_k<<<dim3(DH / 32, DH / 32, NEXP), tb>>>(We1, We1h, We1l, DH, DH, DH, (size_t)DH * DH); // 4
    mma_gemm<EPI_RELU><<<dim3(8, 32), 128, SMEMSZ>>>(                                            // 5: base2
        h1h, h1l, DH, 0, Wb2h, Wb2l, DH, 0, bb2, 0, DH,
        nullptr, hh, hl, DH, 0, nullptr, nullptr);
    transpose_split_k<<<dim3(DH / 32, DH / 32, NEXP), tb>>>(We2, We2h, We2l, DH, DH, DH, (size_t)DH * DH); // 6

    // all experts e1: one GEMM, N = 8192
    mma_gemm<EPI_RELU><<<dim3(NDH8 / 128, 32), 128, SMEMSZ>>>(                                   // 7
        hh, hl, DH, 0, We1h, We1l, DH, 0, be1, 0, DH,
        nullptr, e1h, e1l, NDH8, 0, nullptr, nullptr);

    // all experts e2: z-batched block-diagonal GEMM
    mma_gemm<EPI_RELU><<<dim3(DH / 128, 32, NEXP), 128, SMEMSZ>>>(                               // 8
        e1h, e1l, NDH8, DH, We2h, We2l, DH, DH * DH, be2, DH, DH,
        nullptr, e2h, e2l, NDH8, DH, nullptr, nullptr);

    prep_k<<<1, 256>>>(Wq, bq, bk, task);                                                        // 9
    wn_k<<<NEXP * DH / 8, 256>>>(Wk);                                                            // 10
    expkq_scale_k<<<dim3(BATCH / 8, NEXP), 256>>>();                                             // 11

    transpose_split_k<<<dim3(DH / 32, DVV / 32, NEXP), tb>>>(Wv, Wvh, Wvl, DH, DVV, NDH8, (size_t)DH); // 12

    // fused v-sum: single GEMM over K = 8192
    mma_gemm<EPI_VSUM><<<dim3(DVV / 128, 32), 128, SMEMSZ>>>(                                    // 13
        vth, vtl, NDH8, 0, Wvh, Wvl, NDH8, 0, nullptr, 0, NDH8,
        nullptr, rh, rl, DVV, 0, sc, bv);

    transpose_split_k<<<dim3(DVV / 32, DH / 32, 1), tb>>>(Wt1, Wt1h, Wt1l, DVV, DH, DVV, 0);     // 14
    mma_gemm<EPI_RELU><<<dim3(DH / 128, 32), 128, SMEMSZ>>>(                                     // 15
        rh, rl, DVV, 0, Wt1h, Wt1l, DVV, 0, bt1, 0, DVV,
        nullptr, th, tl, DH, 0, nullptr, nullptr);

    transpose_split_k<<<dim3(DH / 32, NOUT / 32, 1), tb>>>(Wl, Wlh, Wll, DH, NOUT, DH, 0);       // 16
    mma_gemm<EPI_SPLIT><<<dim3(1, 32), 128, SMEMSZ>>>(                                           // 17
        th, tl, DH, 0, Wlh, Wll, DH, 0, bl, 0, DH,
        out, nullptr, nullptr, NOUT, 0, nullptr, nullptr);
}

// round 10
// speedup vs baseline: 1.4924x; 1.3684x over previous
#include <cuda_runtime.h>
#include <cuda_fp16.h>
#include <math.h>
#include <stdint.h>

#define BATCH  4096
#define OBSD   512
#define DH     1024
#define NEXP   8
#define DKK    256
#define DVV    1024
#define NTASKS 10
#define NOUT   128
#define NDH8   (NEXP * DH)          // 8192

// ------------------------- scratch (device globals) ------------------------
// activations: fp16 hi/lo rails
__device__ __half g_xh [BATCH*OBSD], g_xl [BATCH*OBSD];
__device__ __half g_h1h[BATCH*DH],   g_h1l[BATCH*DH];
__device__ __half g_hh [BATCH*DH],   g_hl [BATCH*DH];
__device__ __half g_e1h[(size_t)BATCH*NDH8], g_e1l[(size_t)BATCH*NDH8];
__device__ __half g_e2h[(size_t)BATCH*NDH8], g_e2l[(size_t)BATCH*NDH8];
__device__ __half g_vth[(size_t)BATCH*NDH8], g_vtl[(size_t)BATCH*NDH8];
__device__ __half g_rh [BATCH*DVV],  g_rl [BATCH*DVV];
__device__ __half g_th [BATCH*DH],   g_tl [BATCH*DH];

// weights: single fp16 (transposed [N,K])
__device__ __half g_Wb1t[DH*OBSD];
__device__ __half g_Wb2t[DH*DH];
__device__ __half g_We1t[NEXP*DH*DH];
__device__ __half g_We2t[NEXP*DH*DH];
__device__ __half g_Wvt [(size_t)DVV*NDH8];
__device__ __half g_Wt1t[DH*DVV];
__device__ __half g_Wlt [NOUT*DH];

__device__ float g_q[DKK], g_wn[NEXP*DH], g_cn[NEXP], g_s[NEXP*BATCH];

// ------------------------- PTX helpers -------------------------------------
__device__ __forceinline__ uint32_t smem_u32(const void* p) {
    uint32_t a;
    asm("{ .reg .u64 t; cvta.to.shared.u64 t, %1; cvt.u32.u64 %0, t; }" : "=r"(a) : "l"(p));
    return a;
}
__device__ __forceinline__ void cpa16(uint32_t dst, const void* src) {
    asm volatile("cp.async.cg.shared.global [%0], [%1], 16;" :: "r"(dst), "l"(src));
}
#define CP_COMMIT() asm volatile("cp.async.commit_group;" ::: "memory")
#define CP_WAIT0()  asm volatile("cp.async.wait_group 0;" ::: "memory")
#define CP_WAIT1()  asm volatile("cp.async.wait_group 1;" ::: "memory")

#define LDSM4(r0, r1, r2, r3, addr) \
    asm volatile("ldmatrix.sync.aligned.m8n8.x4.shared.b16 {%0,%1,%2,%3}, [%4];" \
                 : "=r"(r0), "=r"(r1), "=r"(r2), "=r"(r3) : "r"(addr))

#define MMA_F16(d, a, b0v, b1v) \
    asm volatile("mma.sync.aligned.m16n8k16.row.col.f32.f16.f16.f32 " \
                 "{%0,%1,%2,%3},{%4,%5,%6,%7},{%8,%9},{%0,%1,%2,%3};" \
                 : "+f"((d)[0]), "+f"((d)[1]), "+f"((d)[2]), "+f"((d)[3]) \
                 : "r"((a)[0]), "r"((a)[1]), "r"((a)[2]), "r"((a)[3]), \
                   "r"(b0v), "r"(b1v))

// ------------------------- mma.sync fp16x2 GEMM -----------------------------
// C = epi( (Ah+Al) @ Bw^T + bias ),  A rails fp16 [M,K], Bw single fp16 [N,K].
// CTA tile 128x128, 128 threads (4 warps, 2x2 grid of 64x64 warp tiles).
// Pad-free XOR swizzle: unit' = unit ^ ((row>>1)&3), 64B rows.
enum { EPI_RELU = 0, EPI_VSUM = 1, EPI_SPLIT = 2 };

#define TILEB  8192                       // 128 rows * 64B
#define STAGEB (3 * TILEB)                // Ah, Al, Bw = 24 KB
#define NSTAGE 3
#define SMEMSZ (NSTAGE * STAGEB)          // 73728

template <int EPI>
__global__ __launch_bounds__(128, 2)
void mma_gemm(const __half* __restrict__ Ah, const __half* __restrict__ Al,
              int lda, int aoffz,
              const __half* __restrict__ Bw,
              int ldb, int boffz,
              const float* __restrict__ bias, int biasoffz,
              int K,
              float* __restrict__ Cf,
              __half* __restrict__ Ch, __half* __restrict__ Cl,
              int ldc, int coffz,
              const float* __restrict__ sarr, const float* __restrict__ bvv)
{
    extern __shared__ char smem[];
    const uint32_t sbuf = smem_u32(smem);
    const int tid = threadIdx.x, wid = tid >> 5, lane = tid & 31;
    const int z = blockIdx.z;
    const int m0 = blockIdx.y * 128, n0 = blockIdx.x * 128;
    const int warp_m = (wid >> 1) * 64;
    const int warp_n = (wid & 1) * 64;

    const __half* Abase_h = Ah + (size_t)m0 * lda + (size_t)z * aoffz;
    const __half* Abase_l = Al + (size_t)m0 * lda + (size_t)z * aoffz;
    const __half* Bbase   = Bw + (size_t)z * boffz + (size_t)n0 * ldb;

    float acc[4][8][4];
#pragma unroll
    for (int a = 0; a < 4; a++)
#pragma unroll
        for (int b = 0; b < 8; b++)
#pragma unroll
            for (int c = 0; c < 4; c++) acc[a][b][c] = 0.f;

    const int KT = K >> 5;

    auto load_stage = [&](int kt, int s) {
        const uint32_t base = sbuf + s * STAGEB;
        const int k0 = kt << 5;
#pragma unroll
        for (int part = 0; part < 3; part++) {
            const __half* src = (part == 0 ? Abase_h : part == 1 ? Abase_l : Bbase);
            const int ld = (part < 2) ? lda : ldb;
            const uint32_t dstb = base + part * TILEB;
#pragma unroll
            for (int i = 0; i < 4; i++) {
                int idx = i * 128 + tid;           // 512 granules of 16B
                int row = idx >> 2, g = idx & 3;
                int unit = g ^ ((row >> 1) & 3);
                cpa16(dstb + (uint32_t)(row * 64 + unit * 16),
                      src + (size_t)row * ld + k0 + g * 8);
            }
        }
        CP_COMMIT();
    };

    auto a_addr = [&](uint32_t base, int kk, int mt) -> uint32_t {
        const uint32_t arow = warp_m + mt * 16 + ((lane >> 3) & 1) * 8 + (lane & 7);
        const uint32_t cu = (kk * 2 + (lane >> 4)) ^ ((arow >> 1) & 3);
        return base + arow * 64 + cu * 16;
    };

    load_stage(0, 0);
    load_stage(1, 1);

    int s = 0, ls = 2;
    for (int kt = 0; kt < KT; kt++) {
        if (kt == KT - 1) { CP_WAIT0(); } else { CP_WAIT1(); }
        __syncthreads();

        const uint32_t base = sbuf + s * STAGEB;
#pragma unroll
        for (int kk = 0; kk < 2; kk++) {
            uint32_t bh[4][4];
#pragma unroll
            for (int np = 0; np < 4; np++) {
                const uint32_t nrow = warp_n + np * 16 + ((lane >> 4) & 1) * 8 + (lane & 7);
                const uint32_t cu = (kk * 2 + ((lane >> 3) & 1)) ^ ((nrow >> 1) & 3);
                const uint32_t bd = base + 2 * TILEB + nrow * 64 + cu * 16;
                LDSM4(bh[np][0], bh[np][1], bh[np][2], bh[np][3], bd);
            }
            uint32_t ah[2][4], al[2][4];
            {
                const uint32_t ad = a_addr(base, kk, 0);
                LDSM4(ah[0][0], ah[0][1], ah[0][2], ah[0][3], ad);
                LDSM4(al[0][0], al[0][1], al[0][2], al[0][3], ad + TILEB);
            }
#pragma unroll
            for (int mt = 0; mt < 4; mt++) {
                const int cur = mt & 1, nxt = cur ^ 1;
                if (mt < 3) {
                    const uint32_t ad = a_addr(base, kk, mt + 1);
                    LDSM4(ah[nxt][0], ah[nxt][1], ah[nxt][2], ah[nxt][3], ad);
                    LDSM4(al[nxt][0], al[nxt][1], al[nxt][2], al[nxt][3], ad + TILEB);
                }
                // pass 1: Ah x Bw
#pragma unroll
                for (int np = 0; np < 4; np++) {
                    MMA_F16(acc[mt][np * 2],     ah[cur], bh[np][0], bh[np][1]);
                    MMA_F16(acc[mt][np * 2 + 1], ah[cur], bh[np][2], bh[np][3]);
                }
                // pass 2: Al x Bw
#pragma unroll
                for (int np = 0; np < 4; np++) {
                    MMA_F16(acc[mt][np * 2],     al[cur], bh[np][0], bh[np][1]);
                    MMA_F16(acc[mt][np * 2 + 1], al[cur], bh[np][2], bh[np][3]);
                }
            }
        }
        if (kt + 2 < KT) load_stage(kt + 2, ls);
        s  = (s  == NSTAGE - 1) ? 0 : s + 1;
        ls = (ls == NSTAGE - 1) ? 0 : ls + 1;
    }

    // ------------- epilogue -------------
    const int tr = lane >> 2, tc = (lane & 3) * 2;
#pragma unroll
    for (int mt = 0; mt < 4; mt++) {
#pragma unroll
        for (int half2i = 0; half2i < 2; half2i++) {
            const int r = m0 + warp_m + mt * 16 + tr + half2i * 8;
            float sv8[NEXP];
            if (EPI == EPI_VSUM) {
#pragma unroll
                for (int n = 0; n < NEXP; n++) sv8[n] = sarr[n * BATCH + r];
            }
#pragma unroll
            for (int j = 0; j < 8; j++) {
                const int col = n0 + warp_n + j * 8 + tc;
                float v0 = acc[mt][j][half2i * 2];
                float v1 = acc[mt][j][half2i * 2 + 1];

                if (EPI == EPI_RELU) {
                    v0 += bias[(size_t)z * biasoffz + col];
                    v1 += bias[(size_t)z * biasoffz + col + 1];
                    v0 = fmaxf(v0, 0.f); v1 = fmaxf(v1, 0.f);
                    __half h0 = __float2half_rn(v0);
                    __half h1 = __float2half_rn(v1);
                    __half l0 = __float2half_rn(v0 - __half2float(h0));
                    __half l1 = __float2half_rn(v1 - __half2float(h1));
                    size_t o = (size_t)r * ldc + (size_t)z * coffz + col;
                    *(__half2*)(Ch + o) = __halves2half2(h0, h1);
                    *(__half2*)(Cl + o) = __halves2half2(l0, l1);
                } else if (EPI == EPI_VSUM) {
#pragma unroll
                    for (int n = 0; n < NEXP; n++) {
                        v0 += bvv[n * DVV + col]     * sv8[n];
                        v1 += bvv[n * DVV + col + 1] * sv8[n];
                    }
                    __half h0 = __float2half_rn(v0);
                    __half h1 = __float2half_rn(v1);
                    __half l0 = __float2half_rn(v0 - __half2float(h0));
                    __half l1 = __float2half_rn(v1 - __half2float(h1));
                    size_t o = (size_t)r * ldc + col;
                    *(__half2*)(Ch + o) = __halves2half2(h0, h1);
                    *(__half2*)(Cl + o) = __halves2half2(l0, l1);
                } else {   // EPI_SPLIT: out = [mean | std | log_std], each [B,64]
                    v0 += bias[col]; v1 += bias[col + 1];
                    if (col < 64) {
                        Cf[(size_t)r * 64 + col]     = v0;
                        Cf[(size_t)r * 64 + col + 1] = v1;
                    } else {
                        float l0 = fminf(fmaxf(v0, -20.f), 2.f);
                        float l1 = fminf(fmaxf(v1, -20.f), 2.f);
                        Cf[(size_t)BATCH * 64 + (size_t)r * 64 + (col - 64)]     = expf(l0);
                        Cf[(size_t)BATCH * 64 + (size_t)r * 64 + (col - 63)]     = expf(l1);
                        Cf[(size_t)2 * BATCH * 64 + (size_t)r * 64 + (col - 64)] = l0;
                        Cf[(size_t)2 * BATCH * 64 + (size_t)r * 64 + (col - 63)] = l1;
                    }
                }
            }
        }
    }
}

// ------------------------- prep kernels ------------------------------------
// W[K,N] fp32 -> T[N,K] single fp16 (transpose + round)
__global__ void transpose_f16_k(const float* __restrict__ W,
                                __half* __restrict__ T,
                                int K, int N, int ors, size_t zoff)
{
    __shared__ float tile[32][33];
    const int z = blockIdx.z;
    const float* Wb = W + (size_t)z * K * N;
    const int k0 = blockIdx.x * 32, n0 = blockIdx.y * 32;
    const int tx = threadIdx.x, ty = threadIdx.y;   // 16 x 16
#pragma unroll
    for (int ii = 0; ii < 2; ii++)
#pragma unroll
        for (int jj = 0; jj < 2; jj++)
            tile[ty + 16 * ii][tx + 16 * jj] =
                Wb[(size_t)(k0 + ty + 16 * ii) * N + n0 + tx + 16 * jj];
    __syncthreads();
#pragma unroll
    for (int ii = 0; ii < 2; ii++) {
        const int i = ty + 16 * ii;
        float v0 = tile[tx * 2][i], v1 = tile[tx * 2 + 1][i];
        size_t o = (size_t)z * zoff + (size_t)(n0 + i) * ors + k0 + tx * 2;
        *(__half2*)(T + o) = __halves2half2(__float2half_rn(v0), __float2half_rn(v1));
    }
}

__global__ void split_k(const float* __restrict__ X, __half* __restrict__ Xh,
                        __half* __restrict__ Xl, int n)
{
    int i = (blockIdx.x * 256 + threadIdx.x) * 4;
    if (i < n) {
        float4 v = *(const float4*)(X + i);
        __half h0 = __float2half_rn(v.x), h1 = __float2half_rn(v.y);
        __half h2 = __float2half_rn(v.z), h3 = __float2half_rn(v.w);
        __half l0 = __float2half_rn(v.x - __half2float(h0));
        __half l1 = __float2half_rn(v.y - __half2float(h1));
        __half l2 = __float2half_rn(v.z - __half2float(h2));
        __half l3 = __float2half_rn(v.w - __half2float(h3));
        __half2 hp0 = __halves2half2(h0, h1), hp1 = __halves2half2(h2, h3);
        __half2 lp0 = __halves2half2(l0, l1), lp1 = __halves2half2(l2, l3);
        uint2 hu, lu;
        hu.x = *(uint32_t*)&hp0; hu.y = *(uint32_t*)&hp1;
        lu.x = *(uint32_t*)&lp0; lu.y = *(uint32_t*)&lp1;
        *(uint2*)(Xh + i) = hu;
        *(uint2*)(Xl + i) = lu;
    }
}

// q = Wq[t][t,:] + bq[t];  cn[n] = dot(bk[n], q)
__global__ void prep_k(const float* __restrict__ Wq, const float* __restrict__ bq,
                       const float* __restrict__ bk, const int* __restrict__ task_id)
{
    __shared__ float qs[DKK];
    const int t = *task_id;
    const int tid = threadIdx.x;
    float qv = Wq[(size_t)(t * NTASKS + t) * DKK + tid] + bq[(size_t)t * DKK + tid];
    g_q[tid] = qv;
    qs[tid]  = qv;
    __syncthreads();
    const int w = tid >> 5, lane = tid & 31;
    float sum = 0.f;
#pragma unroll
    for (int k = lane; k < DKK; k += 32) sum += bk[(size_t)w * DKK + k] * qs[k];
#pragma unroll
    for (int o = 16; o; o >>= 1) sum += __shfl_xor_sync(0xffffffffu, sum, o);
    if (lane == 0) g_cn[w] = sum;
}

// wn[i] = dot(Wk[i,:], q)
__global__ void wn_k(const float* __restrict__ Wk)
{
    const int tid = threadIdx.x, w = tid >> 5, lane = tid & 31;
    const int row = blockIdx.x * 8 + w;
    const float* wr = Wk + (size_t)row * DKK;
    float sum = 0.f;
#pragma unroll
    for (int k = lane; k < DKK; k += 32) sum += wr[k] * g_q[k];
#pragma unroll
    for (int o = 16; o; o >>= 1) sum += __shfl_xor_sync(0xffffffffu, sum, o);
    if (lane == 0) g_wn[row] = sum;
}

// fused: s[n][b] = dot(e2[b, n*DH..], wn[n]) + cn[n], then
// vt[b, n*DH+d] = split(e2[b,n*DH+d] * s[n][b]).
__global__ void expkq_scale_k()
{
    __shared__ uint32_t shh[8][512], shl[8][512];
    const int tid = threadIdx.x, w = tid >> 5, lane = tid & 31;
    const int row = blockIdx.x * 8 + w;
    const int n = blockIdx.y;
    const size_t base = (size_t)row * NDH8 + (size_t)n * DH;
    const float* wn = g_wn + n * DH;
    float sum = 0.f;
#pragma unroll 4
    for (int it = 0; it < 16; it++) {
        const int k2 = it * 32 + lane;
        uint32_t h2 = *(const uint32_t*)(g_e2h + base + k2 * 2);
        uint32_t l2 = *(const uint32_t*)(g_e2l + base + k2 * 2);
        shh[w][k2] = h2; shl[w][k2] = l2;
        float2 hb = __half22float2(*(__half2*)&h2);
        float2 lb = __half22float2(*(__half2*)&l2);
        float2 wv = *(const float2*)(wn + k2 * 2);
        sum += (hb.x + lb.x) * wv.x + (hb.y + lb.y) * wv.y;
    }
#pragma unroll
    for (int o = 16; o; o >>= 1) sum += __shfl_xor_sync(0xffffffffu, sum, o);
    const float s = sum + g_cn[n];
    if (lane == 0) g_s[n * BATCH + row] = s;
#pragma unroll 4
    for (int it = 0; it < 16; it++) {
        const int k2 = it * 32 + lane;
        uint32_t h2 = shh[w][k2], l2 = shl[w][k2];
        float2 hb = __half22float2(*(__half2*)&h2);
        float2 lb = __half22float2(*(__half2*)&l2);
        float v0 = (hb.x + lb.x) * s;
        float v1 = (hb.y + lb.y) * s;
        __half hh0 = __float2half_rn(v0), hh1 = __float2half_rn(v1);
        __half ll0 = __float2half_rn(v0 - __half2float(hh0));
        __half ll1 = __float2half_rn(v1 - __half2float(hh1));
        *(__half2*)(g_vth + base + k2 * 2) = __halves2half2(hh0, hh1);
        *(__half2*)(g_vtl + base + k2 * 2) = __halves2half2(ll0, ll1);
    }
}

// ------------------------- launch ------------------------------------------
extern "C" void kernel_launch(void* const* d_in, const int* in_sizes, int n_in,
                              void* d_out, int out_size)
{
    const float* x    = (const float*)d_in[0];
    const int*   task = (const int*)  d_in[1];
    const float* Wb1  = (const float*)d_in[2];
    const float* bb1  = (const float*)d_in[3];
    const float* Wb2  = (const float*)d_in[4];
    const float* bb2  = (const float*)d_in[5];
    const float* We1  = (const float*)d_in[6];
    const float* be1  = (const float*)d_in[7];
    const float* We2  = (const float*)d_in[8];
    const float* be2  = (const float*)d_in[9];
    const float* Wv   = (const float*)d_in[10];
    const float* bv   = (const float*)d_in[11];
    const float* Wk   = (const float*)d_in[12];
    const float* bk   = (const float*)d_in[13];
    const float* Wq   = (const float*)d_in[14];
    const float* bq   = (const float*)d_in[15];
    const float* Wt1  = (const float*)d_in[16];
    const float* bt1  = (const float*)d_in[17];
    const float* Wl   = (const float*)d_in[18];
    const float* bl   = (const float*)d_in[19];
    float* out = (float*)d_out;

#define SYM(p, s) do { void* _t; cudaGetSymbolAddress(&_t, s); p = (decltype(p))_t; } while (0)
    __half *xh, *xl, *h1h, *h1l, *hh, *hl, *e1h, *e1l, *e2h, *e2l;
    __half *vth, *vtl, *rh, *rl, *th, *tl;
    __half *Wb1t, *Wb2t, *We1t, *We2t, *Wvt, *Wt1t, *Wlt;
    float *sc;
    SYM(xh, g_xh);  SYM(xl, g_xl);  SYM(h1h, g_h1h); SYM(h1l, g_h1l);
    SYM(hh, g_hh);  SYM(hl, g_hl);  SYM(e1h, g_e1h); SYM(e1l, g_e1l);
    SYM(e2h, g_e2h); SYM(e2l, g_e2l); SYM(vth, g_vth); SYM(vtl, g_vtl);
    SYM(rh, g_rh);  SYM(rl, g_rl);  SYM(th, g_th);  SYM(tl, g_tl);
    SYM(Wb1t, g_Wb1t); SYM(Wb2t, g_Wb2t); SYM(We1t, g_We1t); SYM(We2t, g_We2t);
    SYM(Wvt, g_Wvt); SYM(Wt1t, g_Wt1t); SYM(Wlt, g_Wlt); SYM(sc, g_s);

    cudaFuncSetAttribute(mma_gemm<EPI_RELU >, cudaFuncAttributeMaxDynamicSharedMemorySize, SMEMSZ);
    cudaFuncSetAttribute(mma_gemm<EPI_VSUM >, cudaFuncAttributeMaxDynamicSharedMemorySize, SMEMSZ);
    cudaFuncSetAttribute(mma_gemm<EPI_SPLIT>, cudaFuncAttributeMaxDynamicSharedMemorySize, SMEMSZ);

    dim3 tb(16, 16);

    split_k<<<(BATCH * OBSD / 4 + 255) / 256, 256>>>(x, xh, xl, BATCH * OBSD);                   // 0
    transpose_f16_k<<<dim3(OBSD / 32, DH / 32, 1),  tb>>>(Wb1, Wb1t, OBSD, DH, OBSD, 0);          // 1
    transpose_f16_k<<<dim3(DH / 32, DH / 32, 1),    tb>>>(Wb2, Wb2t, DH, DH, DH, 0);              // 2
    mma_gemm<EPI_RELU><<<dim3(8, 32), 128, SMEMSZ>>>(                                             // 3: base1
        xh, xl, OBSD, 0, Wb1t, OBSD, 0, bb1, 0, OBSD,
        nullptr, h1h, h1l, DH, 0, nullptr, nullptr);
    transpose_f16_k<<<dim3(DH / 32, DH / 32, NEXP), tb>>>(We1, We1t, DH, DH, DH, (size_t)DH * DH); // 4
    mma_gemm<EPI_RELU><<<dim3(8, 32), 128, SMEMSZ>>>(                                             // 5: base2 (profiled)
        h1h, h1l, DH, 0, Wb2t, DH, 0, bb2, 0, DH,
        nullptr, hh, hl, DH, 0, nullptr, nullptr);
    transpose_f16_k<<<dim3(DH / 32, DH / 32, NEXP), tb>>>(We2, We2t, DH, DH, DH, (size_t)DH * DH); // 6

    // all experts e1: one GEMM, N = 8192
    mma_gemm<EPI_RELU><<<dim3(NDH8 / 128, 32), 128, SMEMSZ>>>(                                    // 7
        hh, hl, DH, 0, We1t, DH, 0, be1, 0, DH,
        nullptr, e1h, e1l, NDH8, 0, nullptr, nullptr);

    // all experts e2: z-batched block-diagonal GEMM
    mma_gemm<EPI_RELU><<<dim3(DH / 128, 32, NEXP), 128, SMEMSZ>>>(                                // 8
        e1h, e1l, NDH8, DH, We2t, DH, DH * DH, be2, DH, DH,
        nullptr, e2h, e2l, NDH8, DH, nullptr, nullptr);

    prep_k<<<1, 256>>>(Wq, bq, bk, task);                                                         // 9
    wn_k<<<NEXP * DH / 8, 256>>>(Wk);                                                             // 10
    expkq_scale_k<<<dim3(BATCH / 8, NEXP), 256>>>();                                              // 11

    transpose_f16_k<<<dim3(DH / 32, DVV / 32, NEXP), tb>>>(Wv, Wvt, DH, DVV, NDH8, (size_t)DH);   // 12

    // fused v-sum: single GEMM over K = 8192, bias = sum_n bv[n]*s[n,b] in epilogue
    mma_gemm<EPI_VSUM><<<dim3(DVV / 128, 32), 128, SMEMSZ>>>(                                     // 13
        vth, vtl, NDH8, 0, Wvt, NDH8, 0, nullptr, 0, NDH8,
        nullptr, rh, rl, DVV, 0, sc, bv);

    transpose_f16_k<<<dim3(DVV / 32, DH / 32, 1), tb>>>(Wt1, Wt1t, DVV, DH, DVV, 0);              // 14
    mma_gemm<EPI_RELU><<<dim3(DH / 128, 32), 128, SMEMSZ>>>(                                      // 15
        rh, rl, DVV, 0, Wt1t, DVV, 0, bt1, 0, DVV,
        nullptr, th, tl, DH, 0, nullptr, nullptr);

    transpose_f16_k<<<dim3(DH / 32, NOUT / 32, 1), tb>>>(Wl, Wlt, DH, NOUT, DH, 0);               // 16
    mma_gemm<EPI_SPLIT><<<dim3(1, 32), 128, SMEMSZ>>>(                                            // 17
        th, tl, DH, 0, Wlt, DH, 0, bl, 0, DH,
        out, nullptr, nullptr, NOUT, 0, nullptr, nullptr);
}

// round 11
// speedup vs baseline: 2.3553x; 1.5782x over previous
#include <cuda_runtime.h>
#include <cuda_fp16.h>
#include <math.h>
#include <stdint.h>

#define BATCH  4096
#define OBSD   512
#define DH     1024
#define NEXP   8
#define DKK    256
#define DVV    1024
#define NTASKS 10
#define NOUT   128
#define NDH8   (NEXP * DH)          // 8192

// ------------------------- scratch (device globals) ------------------------
__device__ __half g_xh [BATCH*OBSD], g_xl [BATCH*OBSD];
__device__ __half g_h1h[BATCH*DH],   g_h1l[BATCH*DH];
__device__ __half g_hh [BATCH*DH];                      // single rail
__device__ __half g_e1h[(size_t)BATCH*NDH8];            // single rail
__device__ __half g_e2h[(size_t)BATCH*NDH8];            // single rail
__device__ __half g_vth[(size_t)BATCH*NDH8];            // single rail
__device__ __half g_rh [BATCH*DVV],  g_rl [BATCH*DVV];
__device__ __half g_th [BATCH*DH],   g_tl [BATCH*DH];

// weights: exact layers get hi/lo rails, big layers single fp16 (transposed [N,K])
__device__ __half g_Wb1h[DH*OBSD],  g_Wb1l[DH*OBSD];
__device__ __half g_Wb2h[DH*DH],    g_Wb2l[DH*DH];
__device__ __half g_We1t[NEXP*DH*DH];
__device__ __half g_We2t[NEXP*DH*DH];
__device__ __half g_Wvt [(size_t)DVV*NDH8];
__device__ __half g_Wt1h[DH*DVV],   g_Wt1l[DH*DVV];
__device__ __half g_Wlh [NOUT*DH],  g_Wll [NOUT*DH];

__device__ float g_q[DKK], g_wn[NEXP*DH], g_cn[NEXP], g_s[NEXP*BATCH];

// ------------------------- PTX helpers -------------------------------------
__device__ __forceinline__ uint32_t smem_u32(const void* p) {
    uint32_t a;
    asm("{ .reg .u64 t; cvta.to.shared.u64 t, %1; cvt.u32.u64 %0, t; }" : "=r"(a) : "l"(p));
    return a;
}
__device__ __forceinline__ void cpa16(uint32_t dst, const void* src) {
    asm volatile("cp.async.cg.shared.global [%0], [%1], 16;" :: "r"(dst), "l"(src));
}
#define CP_COMMIT() asm volatile("cp.async.commit_group;" ::: "memory")
#define CP_WAIT0()  asm volatile("cp.async.wait_group 0;" ::: "memory")
#define CP_WAIT1()  asm volatile("cp.async.wait_group 1;" ::: "memory")

#define LDSM4(r0, r1, r2, r3, addr) \
    asm volatile("ldmatrix.sync.aligned.m8n8.x4.shared.b16 {%0,%1,%2,%3}, [%4];" \
                 : "=r"(r0), "=r"(r1), "=r"(r2), "=r"(r3) : "r"(addr))

#define MMA_F16(d, a, b0v, b1v) \
    asm volatile("mma.sync.aligned.m16n8k16.row.col.f32.f16.f16.f32 " \
                 "{%0,%1,%2,%3},{%4,%5,%6,%7},{%8,%9},{%0,%1,%2,%3};" \
                 : "+f"((d)[0]), "+f"((d)[1]), "+f"((d)[2]), "+f"((d)[3]) \
                 : "r"((a)[0]), "r"((a)[1]), "r"((a)[2]), "r"((a)[3]), \
                   "r"(b0v), "r"(b1v))

// ------------------------- mma.sync fp16 GEMM ------------------------------
// P3=true : exact  — A rails (Ah,Al) x W rails (Bh,Bl), 3 passes.
// P3=false: fast   — single rails, 1 pass.
// CTA 128x128, 128 threads, 4 warps of 64x64.  XOR-swizzled 64B-row tiles.
enum { EPI_RELU_R = 0, EPI_RELU_S = 1, EPI_VSUM = 2, EPI_SPLIT = 3 };

#define TILEB  8192                       // 128 rows * 64B
#define NSTAGE 3

template <int EPI, bool P3>
__global__ __launch_bounds__(128, 2)
void mma_gemm(const __half* __restrict__ Ah, const __half* __restrict__ Al,
              int lda, int aoffz,
              const __half* __restrict__ Bh, const __half* __restrict__ Bl,
              int ldb, int boffz,
              const float* __restrict__ bias, int biasoffz,
              int K,
              float* __restrict__ Cf,
              __half* __restrict__ Ch, __half* __restrict__ Cl,
              int ldc, int coffz,
              const float* __restrict__ sarr, const float* __restrict__ bvv)
{
    constexpr int NPART = P3 ? 4 : 2;
    constexpr uint32_t STG = NPART * TILEB;

    extern __shared__ char smem[];
    const uint32_t sbuf = smem_u32(smem);
    const int tid = threadIdx.x, wid = tid >> 5, lane = tid & 31;
    const int z = blockIdx.z;
    const int m0 = blockIdx.y * 128, n0 = blockIdx.x * 128;
    const int warp_m = (wid >> 1) * 64;
    const int warp_n = (wid & 1) * 64;

    const __half* Ab_h = Ah + (size_t)m0 * lda + (size_t)z * aoffz;
    const __half* Ab_l = P3 ? (Al + (size_t)m0 * lda + (size_t)z * aoffz) : nullptr;
    const __half* Bb_h = Bh + (size_t)z * boffz + (size_t)n0 * ldb;
    const __half* Bb_l = P3 ? (Bl + (size_t)z * boffz + (size_t)n0 * ldb) : nullptr;

    float acc[4][8][4];
#pragma unroll
    for (int a = 0; a < 4; a++)
#pragma unroll
        for (int b = 0; b < 8; b++)
#pragma unroll
            for (int c = 0; c < 4; c++) acc[a][b][c] = 0.f;

    const int KT = K >> 5;

    auto load_stage = [&](int kt, int s) {
        const uint32_t base = sbuf + s * STG;
        const int k0 = kt << 5;
#pragma unroll
        for (int part = 0; part < NPART; part++) {
            const __half* src;
            int ld;
            if (P3) {
                src = (part == 0 ? Ab_h : part == 1 ? Ab_l : part == 2 ? Bb_h : Bb_l);
                ld = (part < 2) ? lda : ldb;
            } else {
                src = (part == 0 ? Ab_h : Bb_h);
                ld = (part == 0) ? lda : ldb;
            }
            const uint32_t dstb = base + part * TILEB;
#pragma unroll
            for (int i = 0; i < 4; i++) {
                int idx = i * 128 + tid;
                int row = idx >> 2, g = idx & 3;
                int unit = g ^ ((row >> 1) & 3);
                cpa16(dstb + (uint32_t)(row * 64 + unit * 16),
                      src + (size_t)row * ld + k0 + g * 8);
            }
        }
        CP_COMMIT();
    };

    load_stage(0, 0);
    load_stage(1, 1);

    const uint32_t boff = (P3 ? 2 : 1) * TILEB;
    int s = 0, ls = 2;
    for (int kt = 0; kt < KT; kt++) {
        if (kt == KT - 1) { CP_WAIT0(); } else { CP_WAIT1(); }
        __syncthreads();

        const uint32_t base = sbuf + s * STG;
#pragma unroll
        for (int kk = 0; kk < 2; kk++) {
            uint32_t bh[4][4], bl[4][4];
#pragma unroll
            for (int np = 0; np < 4; np++) {
                const uint32_t nrow = warp_n + np * 16 + ((lane >> 4) & 1) * 8 + (lane & 7);
                const uint32_t cu = (kk * 2 + ((lane >> 3) & 1)) ^ ((nrow >> 1) & 3);
                const uint32_t bd = base + boff + nrow * 64 + cu * 16;
                LDSM4(bh[np][0], bh[np][1], bh[np][2], bh[np][3], bd);
                if (P3) LDSM4(bl[np][0], bl[np][1], bl[np][2], bl[np][3], bd + TILEB);
            }
#pragma unroll
            for (int mt = 0; mt < 4; mt++) {
                const uint32_t arow = warp_m + mt * 16 + ((lane >> 3) & 1) * 8 + (lane & 7);
                const uint32_t cu = (kk * 2 + (lane >> 4)) ^ ((arow >> 1) & 3);
                const uint32_t ad = base + arow * 64 + cu * 16;
                uint32_t ah[4], al[4];
                LDSM4(ah[0], ah[1], ah[2], ah[3], ad);
                if (P3) LDSM4(al[0], al[1], al[2], al[3], ad + TILEB);
                // pass 1: Ah x Bh
#pragma unroll
                for (int np = 0; np < 4; np++) {
                    MMA_F16(acc[mt][np * 2],     ah, bh[np][0], bh[np][1]);
                    MMA_F16(acc[mt][np * 2 + 1], ah, bh[np][2], bh[np][3]);
                }
                if (P3) {
                    // pass 2: Ah x Bl
#pragma unroll
                    for (int np = 0; np < 4; np++) {
                        MMA_F16(acc[mt][np * 2],     ah, bl[np][0], bl[np][1]);
                        MMA_F16(acc[mt][np * 2 + 1], ah, bl[np][2], bl[np][3]);
                    }
                    // pass 3: Al x Bh
#pragma unroll
                    for (int np = 0; np < 4; np++) {
                        MMA_F16(acc[mt][np * 2],     al, bh[np][0], bh[np][1]);
                        MMA_F16(acc[mt][np * 2 + 1], al, bh[np][2], bh[np][3]);
                    }
                }
            }
        }
        if (kt + 2 < KT) load_stage(kt + 2, ls);
        s  = (s  == NSTAGE - 1) ? 0 : s + 1;
        ls = (ls == NSTAGE - 1) ? 0 : ls + 1;
    }

    // ------------- epilogue -------------
    const int tr = lane >> 2, tc = (lane & 3) * 2;
#pragma unroll
    for (int mt = 0; mt < 4; mt++) {
#pragma unroll
        for (int hf = 0; hf < 2; hf++) {
            const int r = m0 + warp_m + mt * 16 + tr + hf * 8;
            float sv8[NEXP];
            if (EPI == EPI_VSUM) {
#pragma unroll
                for (int n = 0; n < NEXP; n++) sv8[n] = sarr[n * BATCH + r];
            }
#pragma unroll
            for (int j = 0; j < 8; j++) {
                const int col = n0 + warp_n + j * 8 + tc;
                float v0 = acc[mt][j][hf * 2];
                float v1 = acc[mt][j][hf * 2 + 1];

                if (EPI == EPI_RELU_R || EPI == EPI_RELU_S) {
                    v0 += bias[(size_t)z * biasoffz + col];
                    v1 += bias[(size_t)z * biasoffz + col + 1];
                    v0 = fmaxf(v0, 0.f); v1 = fmaxf(v1, 0.f);
                    __half h0 = __float2half_rn(v0);
                    __half h1 = __float2half_rn(v1);
                    size_t o = (size_t)r * ldc + (size_t)z * coffz + col;
                    *(__half2*)(Ch + o) = __halves2half2(h0, h1);
                    if (EPI == EPI_RELU_R) {
                        __half l0 = __float2half_rn(v0 - __half2float(h0));
                        __half l1 = __float2half_rn(v1 - __half2float(h1));
                        *(__half2*)(Cl + o) = __halves2half2(l0, l1);
                    }
                } else if (EPI == EPI_VSUM) {
#pragma unroll
                    for (int n = 0; n < NEXP; n++) {
                        v0 += bvv[n * DVV + col]     * sv8[n];
                        v1 += bvv[n * DVV + col + 1] * sv8[n];
                    }
                    __half h0 = __float2half_rn(v0);
                    __half h1 = __float2half_rn(v1);
                    __half l0 = __float2half_rn(v0 - __half2float(h0));
                    __half l1 = __float2half_rn(v1 - __half2float(h1));
                    size_t o = (size_t)r * ldc + col;
                    *(__half2*)(Ch + o) = __halves2half2(h0, h1);
                    *(__half2*)(Cl + o) = __halves2half2(l0, l1);
                } else {   // EPI_SPLIT: out = [mean | std | log_std], each [B,64]
                    v0 += bias[col]; v1 += bias[col + 1];
                    if (col < 64) {
                        Cf[(size_t)r * 64 + col]     = v0;
                        Cf[(size_t)r * 64 + col + 1] = v1;
                    } else {
                        float l0 = fminf(fmaxf(v0, -20.f), 2.f);
                        float l1 = fminf(fmaxf(v1, -20.f), 2.f);
                        Cf[(size_t)BATCH * 64 + (size_t)r * 64 + (col - 64)]     = expf(l0);
                        Cf[(size_t)BATCH * 64 + (size_t)r * 64 + (col - 63)]     = expf(l1);
                        Cf[(size_t)2 * BATCH * 64 + (size_t)r * 64 + (col - 64)] = l0;
                        Cf[(size_t)2 * BATCH * 64 + (size_t)r * 64 + (col - 63)] = l1;
                    }
                }
            }
        }
    }
}

// ------------------------- prep kernels ------------------------------------
// W[K,N] fp32 -> T[N,K] fp16 hi/lo rails (transpose + split)
__global__ void transpose_split_k(const float* __restrict__ W,
                                  __half* __restrict__ Th, __half* __restrict__ Tl,
                                  int K, int N, int ors, size_t zoff)
{
    __shared__ float tile[32][33];
    const int z = blockIdx.z;
    const float* Wb = W + (size_t)z * K * N;
    const int k0 = blockIdx.x * 32, n0 = blockIdx.y * 32;
    const int tx = threadIdx.x, ty = threadIdx.y;
#pragma unroll
    for (int ii = 0; ii < 2; ii++)
#pragma unroll
        for (int jj = 0; jj < 2; jj++)
            tile[ty + 16 * ii][tx + 16 * jj] =
                Wb[(size_t)(k0 + ty + 16 * ii) * N + n0 + tx + 16 * jj];
    __syncthreads();
#pragma unroll
    for (int ii = 0; ii < 2; ii++) {
        const int i = ty + 16 * ii;
        float v0 = tile[tx * 2][i], v1 = tile[tx * 2 + 1][i];
        __half h0 = __float2half_rn(v0), h1 = __float2half_rn(v1);
        __half l0 = __float2half_rn(v0 - __half2float(h0));
        __half l1 = __float2half_rn(v1 - __half2float(h1));
        size_t o = (size_t)z * zoff + (size_t)(n0 + i) * ors + k0 + tx * 2;
        *(__half2*)(Th + o) = __halves2half2(h0, h1);
        *(__half2*)(Tl + o) = __halves2half2(l0, l1);
    }
}

// W[K,N] fp32 -> T[N,K] single fp16
__global__ void transpose_f16_k(const float* __restrict__ W, __half* __restrict__ T,
                                int K, int N, int ors, size_t zoff)
{
    __shared__ float tile[32][33];
    const int z = blockIdx.z;
    const float* Wb = W + (size_t)z * K * N;
    const int k0 = blockIdx.x * 32, n0 = blockIdx.y * 32;
    const int tx = threadIdx.x, ty = threadIdx.y;
#pragma unroll
    for (int ii = 0; ii < 2; ii++)
#pragma unroll
        for (int jj = 0; jj < 2; jj++)
            tile[ty + 16 * ii][tx + 16 * jj] =
                Wb[(size_t)(k0 + ty + 16 * ii) * N + n0 + tx + 16 * jj];
    __syncthreads();
#pragma unroll
    for (int ii = 0; ii < 2; ii++) {
        const int i = ty + 16 * ii;
        float v0 = tile[tx * 2][i], v1 = tile[tx * 2 + 1][i];
        size_t o = (size_t)z * zoff + (size_t)(n0 + i) * ors + k0 + tx * 2;
        *(__half2*)(T + o) = __halves2half2(__float2half_rn(v0), __float2half_rn(v1));
    }
}

__global__ void split_k(const float* __restrict__ X, __half* __restrict__ Xh,
                        __half* __restrict__ Xl, int n)
{
    int i = (blockIdx.x * 256 + threadIdx.x) * 4;
    if (i < n) {
        float4 v = *(const float4*)(X + i);
        __half h0 = __float2half_rn(v.x), h1 = __float2half_rn(v.y);
        __half h2 = __float2half_rn(v.z), h3 = __float2half_rn(v.w);
        __half l0 = __float2half_rn(v.x - __half2float(h0));
        __half l1 = __float2half_rn(v.y - __half2float(h1));
        __half l2 = __float2half_rn(v.z - __half2float(h2));
        __half l3 = __float2half_rn(v.w - __half2float(h3));
        __half2 hp0 = __halves2half2(h0, h1), hp1 = __halves2half2(h2, h3);
        __half2 lp0 = __halves2half2(l0, l1), lp1 = __halves2half2(l2, l3);
        uint2 hu, lu;
        hu.x = *(uint32_t*)&hp0; hu.y = *(uint32_t*)&hp1;
        lu.x = *(uint32_t*)&lp0; lu.y = *(uint32_t*)&lp1;
        *(uint2*)(Xh + i) = hu;
        *(uint2*)(Xl + i) = lu;
    }
}

// q = Wq[t][t,:] + bq[t];  cn[n] = dot(bk[n], q)
__global__ void prep_k(const float* __restrict__ Wq, const float* __restrict__ bq,
                       const float* __restrict__ bk, const int* __restrict__ task_id)
{
    __shared__ float qs[DKK];
    const int t = *task_id;
    const int tid = threadIdx.x;
    float qv = Wq[(size_t)(t * NTASKS + t) * DKK + tid] + bq[(size_t)t * DKK + tid];
    g_q[tid] = qv;
    qs[tid]  = qv;
    __syncthreads();
    const int w = tid >> 5, lane = tid & 31;
    float sum = 0.f;
#pragma unroll
    for (int k = lane; k < DKK; k += 32) sum += bk[(size_t)w * DKK + k] * qs[k];
#pragma unroll
    for (int o = 16; o; o >>= 1) sum += __shfl_xor_sync(0xffffffffu, sum, o);
    if (lane == 0) g_cn[w] = sum;
}

// wn[i] = dot(Wk[i,:], q)
__global__ void wn_k(const float* __restrict__ Wk)
{
    const int tid = threadIdx.x, w = tid >> 5, lane = tid & 31;
    const int row = blockIdx.x * 8 + w;
    const float* wr = Wk + (size_t)row * DKK;
    float sum = 0.f;
#pragma unroll
    for (int k = lane; k < DKK; k += 32) sum += wr[k] * g_q[k];
#pragma unroll
    for (int o = 16; o; o >>= 1) sum += __shfl_xor_sync(0xffffffffu, sum, o);
    if (lane == 0) g_wn[row] = sum;
}

// fused: s[n][b] = dot(e2[b, n*DH..], wn[n]) + cn[n], then vt = fp16(e2 * s).
__global__ void expkq_scale_k()
{
    __shared__ uint32_t shh[8][512];
    const int tid = threadIdx.x, w = tid >> 5, lane = tid & 31;
    const int row = blockIdx.x * 8 + w;
    const int n = blockIdx.y;
    const size_t base = (size_t)row * NDH8 + (size_t)n * DH;
    const float* wn = g_wn + n * DH;
    float sum = 0.f;
#pragma unroll 4
    for (int it = 0; it < 16; it++) {
        const int k2 = it * 32 + lane;
        uint32_t h2 = *(const uint32_t*)(g_e2h + base + k2 * 2);
        shh[w][k2] = h2;
        float2 hb = __half22float2(*(__half2*)&h2);
        float2 wv = *(const float2*)(wn + k2 * 2);
        sum += hb.x * wv.x + hb.y * wv.y;
    }
#pragma unroll
    for (int o = 16; o; o >>= 1) sum += __shfl_xor_sync(0xffffffffu, sum, o);
    const float s = sum + g_cn[n];
    if (lane == 0) g_s[n * BATCH + row] = s;
#pragma unroll 4
    for (int it = 0; it < 16; it++) {
        const int k2 = it * 32 + lane;
        uint32_t h2 = shh[w][k2];
        float2 hb = __half22float2(*(__half2*)&h2);
        *(__half2*)(g_vth + base + k2 * 2) =
            __halves2half2(__float2half_rn(hb.x * s), __float2half_rn(hb.y * s));
    }
}

// ------------------------- launch ------------------------------------------
extern "C" void kernel_launch(void* const* d_in, const int* in_sizes, int n_in,
                              void* d_out, int out_size)
{
    const float* x    = (const float*)d_in[0];
    const int*   task = (const int*)  d_in[1];
    const float* Wb1  = (const float*)d_in[2];
    const float* bb1  = (const float*)d_in[3];
    const float* Wb2  = (const float*)d_in[4];
    const float* bb2  = (const float*)d_in[5];
    const float* We1  = (const float*)d_in[6];
    const float* be1  = (const float*)d_in[7];
    const float* We2  = (const float*)d_in[8];
    const float* be2  = (const float*)d_in[9];
    const float* Wv   = (const float*)d_in[10];
    const float* bv   = (const float*)d_in[11];
    const float* Wk   = (const float*)d_in[12];
    const float* bk   = (const float*)d_in[13];
    const float* Wq   = (const float*)d_in[14];
    const float* bq   = (const float*)d_in[15];
    const float* Wt1  = (const float*)d_in[16];
    const float* bt1  = (const float*)d_in[17];
    const float* Wl   = (const float*)d_in[18];
    const float* bl   = (const float*)d_in[19];
    float* out = (float*)d_out;

#define SYM(p, s) do { void* _t; cudaGetSymbolAddress(&_t, s); p = (decltype(p))_t; } while (0)
    __half *xh, *xl, *h1h, *h1l, *hh, *e1h, *e2h, *vth, *rh, *rl, *th, *tl;
    __half *Wb1h, *Wb1l, *Wb2h, *Wb2l, *We1t, *We2t, *Wvt, *Wt1h, *Wt1l, *Wlh, *Wll;
    float *sc;
    SYM(xh, g_xh);  SYM(xl, g_xl);  SYM(h1h, g_h1h); SYM(h1l, g_h1l);
    SYM(hh, g_hh);  SYM(e1h, g_e1h); SYM(e2h, g_e2h); SYM(vth, g_vth);
    SYM(rh, g_rh);  SYM(rl, g_rl);  SYM(th, g_th);  SYM(tl, g_tl);
    SYM(Wb1h, g_Wb1h); SYM(Wb1l, g_Wb1l); SYM(Wb2h, g_Wb2h); SYM(Wb2l, g_Wb2l);
    SYM(We1t, g_We1t); SYM(We2t, g_We2t); SYM(Wvt, g_Wvt);
    SYM(Wt1h, g_Wt1h); SYM(Wt1l, g_Wt1l); SYM(Wlh, g_Wlh); SYM(Wll, g_Wll);
    SYM(sc, g_s);

    const int SMEM_P3 = NSTAGE * 4 * TILEB;   // 98304
    const int SMEM_P1 = NSTAGE * 2 * TILEB;   // 49152
    cudaFuncSetAttribute(mma_gemm<EPI_RELU_R, true >, cudaFuncAttributeMaxDynamicSharedMemorySize, SMEM_P3);
    cudaFuncSetAttribute(mma_gemm<EPI_RELU_S, true >, cudaFuncAttributeMaxDynamicSharedMemorySize, SMEM_P3);
    cudaFuncSetAttribute(mma_gemm<EPI_SPLIT,  true >, cudaFuncAttributeMaxDynamicSharedMemorySize, SMEM_P3);
    cudaFuncSetAttribute(mma_gemm<EPI_RELU_S, false>, cudaFuncAttributeMaxDynamicSharedMemorySize, SMEM_P1);
    cudaFuncSetAttribute(mma_gemm<EPI_VSUM,   false>, cudaFuncAttributeMaxDynamicSharedMemorySize, SMEM_P1);

    dim3 tb(16, 16);

    split_k<<<(BATCH * OBSD / 4 + 255) / 256, 256>>>(x, xh, xl, BATCH * OBSD);
    transpose_split_k<<<dim3(OBSD / 32, DH / 32, 1),  tb>>>(Wb1, Wb1h, Wb1l, OBSD, DH, OBSD, 0);
    transpose_split_k<<<dim3(DH / 32, DH / 32, 1),    tb>>>(Wb2, Wb2h, Wb2l, DH, DH, DH, 0);

    // base1 (exact 3-pass) -> h1 rails
    mma_gemm<EPI_RELU_R, true><<<dim3(8, 32), 128, SMEM_P3>>>(
        xh, xl, OBSD, 0, Wb1h, Wb1l, OBSD, 0, bb1, 0, OBSD,
        nullptr, h1h, h1l, DH, 0, nullptr, nullptr);
    transpose_f16_k<<<dim3(DH / 32, DH / 32, NEXP), tb>>>(We1, We1t, DH, DH, DH, (size_t)DH * DH);

    // base2 (exact 3-pass) -> hh single rail
    mma_gemm<EPI_RELU_S, true><<<dim3(8, 32), 128, SMEM_P3>>>(
        h1h, h1l, DH, 0, Wb2h, Wb2l, DH, 0, bb2, 0, DH,
        nullptr, hh, nullptr, DH, 0, nullptr, nullptr);
    transpose_f16_k<<<dim3(DH / 32, DH / 32, NEXP), tb>>>(We2, We2t, DH, DH, DH, (size_t)DH * DH);

    // e1: one GEMM, N = 8192, single-pass
    mma_gemm<EPI_RELU_S, false><<<dim3(NDH8 / 128, 32), 128, SMEM_P1>>>(
        hh, nullptr, DH, 0, We1t, nullptr, DH, 0, be1, 0, DH,
        nullptr, e1h, nullptr, NDH8, 0, nullptr, nullptr);

    // e2: z-batched block-diagonal, single-pass
    mma_gemm<EPI_RELU_S, false><<<dim3(DH / 128, 32, NEXP), 128, SMEM_P1>>>(
        e1h, nullptr, NDH8, DH, We2t, nullptr, DH, DH * DH, be2, DH, DH,
        nullptr, e2h, nullptr, NDH8, DH, nullptr, nullptr);

    prep_k<<<1, 256>>>(Wq, bq, bk, task);
    wn_k<<<NEXP * DH / 8, 256>>>(Wk);
    expkq_scale_k<<<dim3(BATCH / 8, NEXP), 256>>>();

    transpose_f16_k<<<dim3(DH / 32, DVV / 32, NEXP), tb>>>(Wv, Wvt, DH, DVV, NDH8, (size_t)DH);

    // fused v-sum: single GEMM over K = 8192, single-pass -> res rails
    mma_gemm<EPI_VSUM, false><<<dim3(DVV / 128, 32), 128, SMEM_P1>>>(
        vth, nullptr, NDH8, 0, Wvt, nullptr, NDH8, 0, nullptr, 0, NDH8,
        nullptr, rh, rl, DVV, 0, sc, bv);

    transpose_split_k<<<dim3(DVV / 32, DH / 32, 1), tb>>>(Wt1, Wt1h, Wt1l, DVV, DH, DVV, 0);
    // tower (exact 3-pass) -> th rails
    mma_gemm<EPI_RELU_R, true><<<dim3(DH / 128, 32), 128, SMEM_P3>>>(
        rh, rl, DVV, 0, Wt1h, Wt1l, DVV, 0, bt1, 0, DVV,
        nullptr, th, tl, DH, 0, nullptr, nullptr);

    transpose_split_k<<<dim3(DH / 32, NOUT / 32, 1), tb>>>(Wl, Wlh, Wll, DH, NOUT, DH, 0);
    // head (exact 3-pass)
    mma_gemm<EPI_SPLIT, true><<<dim3(1, 32), 128, SMEM_P3>>>(
        th, tl, DH, 0, Wlh, Wll, DH, 0, bl, 0, DH,
        out, nullptr, nullptr, NOUT, 0, nullptr, nullptr);
}